// round 2
// baseline (speedup 1.0000x reference)
#include <cuda_runtime.h>
#include <cuda_bf16.h>
#include <cstdio>

#define D_MODEL 768
#define RANK    4
#define BATCH   2
#define T_LEN   2048
#define NTOK    (BATCH * T_LEN)        // 4096
#define N_IN    (D_MODEL * RANK * 2)   // 6144

// Scratch (device globals: allocation-free rule)
__device__ float g_xn[(size_t)NTOK * D_MODEL];   // 12.6 MB
__device__ float g_u [(size_t)NTOK * N_IN];      // 100.7 MB
__device__ float g_y [(size_t)NTOK * D_MODEL];   // 12.6 MB

// ---------------------------------------------------------------------------
// RMSNorm: one block per token, 256 threads, 3 elems/thread
// ---------------------------------------------------------------------------
__global__ __launch_bounds__(256) void rmsnorm_kernel(const float* __restrict__ x,
                                                      const float* __restrict__ w) {
    int tok = blockIdx.x;
    const float* xr = x + (size_t)tok * D_MODEL;
    float* o = g_xn + (size_t)tok * D_MODEL;
    int t = threadIdx.x;

    float v[3];
    float ss = 0.f;
#pragma unroll
    for (int i = 0; i < 3; i++) { v[i] = xr[t + 256 * i]; ss += v[i] * v[i]; }

    __shared__ float red[8];
#pragma unroll
    for (int off = 16; off; off >>= 1) ss += __shfl_down_sync(0xffffffffu, ss, off);
    if ((t & 31) == 0) red[t >> 5] = ss;
    __syncthreads();
    if (t < 8) {
        float s = red[t];
#pragma unroll
        for (int off = 4; off; off >>= 1) s += __shfl_down_sync(0xffu, s, off);
        if (t == 0) red[0] = s;
    }
    __syncthreads();
    float scale = rsqrtf(red[0] * (1.0f / D_MODEL) + 1e-6f);
#pragma unroll
    for (int i = 0; i < 3; i++) o[t + 256 * i] = v[i] * scale * w[t + 256 * i];
}

// ---------------------------------------------------------------------------
// SGEMM (NT): C[m,n] = sum_k A[m*K+k] * B[n*K+k]
// 128x128 tile, BK=16, 256 threads, 8x8 per thread
// ---------------------------------------------------------------------------
__global__ __launch_bounds__(256) void sgemm_nt(const float* __restrict__ A,
                                                const float* __restrict__ Bm,
                                                float* __restrict__ C,
                                                int M, int N, int K) {
    const int BM = 128, BN = 128, BK = 16, TM = 8, TN = 8;
    __shared__ float As[BK][BM];
    __shared__ float Bs[BK][BN];

    int tid = threadIdx.x;
    int tx = tid & 15;        // 0..15 -> N groups of 8
    int ty = tid >> 4;        // 0..15 -> M groups of 8

    const float* Ab = A  + (size_t)(blockIdx.y * BM) * K;
    const float* Bb = Bm + (size_t)(blockIdx.x * BN) * K;

    int lrow = tid >> 2;           // 0..63
    int lcol = (tid & 3) * 4;      // 0,4,8,12

    float acc[TM][TN];
#pragma unroll
    for (int i = 0; i < TM; i++)
#pragma unroll
        for (int j = 0; j < TN; j++) acc[i][j] = 0.f;

    for (int k0 = 0; k0 < K; k0 += BK) {
#pragma unroll
        for (int r = 0; r < 2; r++) {
            int row = lrow + 64 * r;
            float4 va = *(const float4*)(Ab + (size_t)row * K + k0 + lcol);
            As[lcol + 0][row] = va.x;
            As[lcol + 1][row] = va.y;
            As[lcol + 2][row] = va.z;
            As[lcol + 3][row] = va.w;
            float4 vb = *(const float4*)(Bb + (size_t)row * K + k0 + lcol);
            Bs[lcol + 0][row] = vb.x;
            Bs[lcol + 1][row] = vb.y;
            Bs[lcol + 2][row] = vb.z;
            Bs[lcol + 3][row] = vb.w;
        }
        __syncthreads();

#pragma unroll
        for (int kk = 0; kk < BK; kk++) {
            float ra[TM], rb[TN];
#pragma unroll
            for (int i = 0; i < TM; i++) ra[i] = As[kk][ty * TM + i];
#pragma unroll
            for (int j = 0; j < TN; j++) rb[j] = Bs[kk][tx * TN + j];
#pragma unroll
            for (int i = 0; i < TM; i++)
#pragma unroll
                for (int j = 0; j < TN; j++) acc[i][j] = fmaf(ra[i], rb[j], acc[i][j]);
        }
        __syncthreads();
    }

    float* Cb = C + (size_t)(blockIdx.y * BM + ty * TM) * N + blockIdx.x * BN + tx * TN;
#pragma unroll
    for (int i = 0; i < TM; i++) {
#pragma unroll
        for (int j = 0; j < TN; j += 4) {
            float4 v = make_float4(acc[i][j], acc[i][j + 1], acc[i][j + 2], acc[i][j + 3]);
            *(float4*)(Cb + (size_t)i * N + j) = v;
        }
    }
}

// ---------------------------------------------------------------------------
// Complex linear recurrence scan: one warp per (b,d), all R=4 ranks per lane.
// Lane l owns timesteps [64l, 64l+64). Two-pass chunked scan with
// Kogge-Stone shuffle carry propagation (coefficient a^(64*off)).
// ---------------------------------------------------------------------------
__global__ __launch_bounds__(256) void scan_kernel(const float* __restrict__ a_p,
                                                   const float* __restrict__ b_p,
                                                   const float* __restrict__ c_p) {
    int warp = (blockIdx.x * blockDim.x + threadIdx.x) >> 5;
    int lane = threadIdx.x & 31;
    if (warp >= BATCH * D_MODEL) return;
    int b = warp / D_MODEL;
    int d = warp % D_MODEL;

    float ar[RANK], ai[RANK], br_[RANK], bi[RANK], cr[RANK], ci[RANK];
#pragma unroll
    for (int r = 0; r < RANK; r++) {
        int idx = (d * RANK + r) * 2;
        ar[r]  = tanhf(a_p[idx + 0]) * 0.97f;
        ai[r]  = tanhf(a_p[idx + 1]) * 0.97f;
        br_[r] = tanhf(b_p[idx + 0]);
        bi[r]  = tanhf(b_p[idx + 1]);
        cr[r]  = tanhf(c_p[idx + 0]);
        ci[r]  = tanhf(c_p[idx + 1]);
    }

    const int CH = T_LEN / 32;                         // 64 steps per lane
    const size_t tstride = (size_t)D_MODEL * RANK * 2; // 6144 floats per t
    const float* ub = g_u + (size_t)b * T_LEN * tstride + (size_t)d * RANK * 2;
    int t0 = lane * CH;

    // ---- pass 1: chunk contribution with zero initial state ----
    float sr[RANK] = {0, 0, 0, 0}, si[RANK] = {0, 0, 0, 0};
    {
        const float* up = ub + (size_t)t0 * tstride;
        for (int i = 0; i < CH; i++) {
            float4 u0 = *(const float4*)(up);
            float4 u1 = *(const float4*)(up + 4);
            float ur[4] = {u0.x, u0.z, u1.x, u1.z};
            float ui[4] = {u0.y, u0.w, u1.y, u1.w};
#pragma unroll
            for (int r = 0; r < RANK; r++) {
                float nsr = ar[r] * sr[r] - ai[r] * si[r] + br_[r] * ur[r] - bi[r] * ui[r];
                float nsi = ar[r] * si[r] + ai[r] * sr[r] + br_[r] * ui[r] + bi[r] * ur[r];
                sr[r] = nsr; si[r] = nsi;
            }
            up += tstride;
        }
    }

    // ---- powers A = a^CH via squaring ----
    float Pr[RANK], Pi[RANK];
#pragma unroll
    for (int r = 0; r < RANK; r++) {
        float pr = ar[r], pi = ai[r];
#pragma unroll
        for (int s = 0; s < 6; s++) { float nr = pr * pr - pi * pi, ni = 2.f * pr * pi; pr = nr; pi = ni; }
        Pr[r] = pr; Pi[r] = pi;
    }

    // ---- Kogge-Stone inclusive scan over lanes (coefficient A^off) ----
    for (int off = 1; off < 32; off <<= 1) {
#pragma unroll
        for (int r = 0; r < RANK; r++) {
            float prr = __shfl_up_sync(0xffffffffu, sr[r], off);
            float pri = __shfl_up_sync(0xffffffffu, si[r], off);
            if (lane >= off) {
                sr[r] += Pr[r] * prr - Pi[r] * pri;
                si[r] += Pr[r] * pri + Pi[r] * prr;
            }
        }
#pragma unroll
        for (int r = 0; r < RANK; r++) {
            float nr = Pr[r] * Pr[r] - Pi[r] * Pi[r];
            float ni = 2.f * Pr[r] * Pi[r];
            Pr[r] = nr; Pi[r] = ni;
        }
    }
    // carry-in = inclusive value of lane-1 (zero for lane 0)
#pragma unroll
    for (int r = 0; r < RANK; r++) {
        float prr = __shfl_up_sync(0xffffffffu, sr[r], 1);
        float pri = __shfl_up_sync(0xffffffffu, si[r], 1);
        sr[r] = (lane == 0) ? 0.f : prr;
        si[r] = (lane == 0) ? 0.f : pri;
    }

    // ---- pass 2: replay with carry, emit y ----
    {
        const float* up = ub + (size_t)t0 * tstride;
        float* yp = g_y + (size_t)(b * T_LEN + t0) * D_MODEL + d;
        for (int i = 0; i < CH; i++) {
            float4 u0 = *(const float4*)(up);
            float4 u1 = *(const float4*)(up + 4);
            float ur[4] = {u0.x, u0.z, u1.x, u1.z};
            float ui[4] = {u0.y, u0.w, u1.y, u1.w};
            float y = 0.f;
#pragma unroll
            for (int r = 0; r < RANK; r++) {
                float nsr = ar[r] * sr[r] - ai[r] * si[r] + br_[r] * ur[r] - bi[r] * ui[r];
                float nsi = ar[r] * si[r] + ai[r] * sr[r] + br_[r] * ui[r] + bi[r] * ur[r];
                sr[r] = nsr; si[r] = nsi;
                y += cr[r] * nsr - ci[r] * nsi;
            }
            *yp = y;
            up += tstride;
            yp += D_MODEL;
        }
    }
}

// ---------------------------------------------------------------------------
extern "C" void kernel_launch(void* const* d_in, const int* in_sizes, int n_in,
                              void* d_out, int out_size) {
    const float* x      = (const float*)d_in[0];
    const float* norm_w = (const float*)d_in[1];
    const float* W_in   = (const float*)d_in[2];
    const float* W_out  = (const float*)d_in[3];
    const float* a_p    = (const float*)d_in[4];
    const float* b_p    = (const float*)d_in[5];
    const float* c_p    = (const float*)d_in[6];
    float* out = (float*)d_out;

    float *xn_ptr, *u_ptr, *y_ptr;
    cudaGetSymbolAddress((void**)&xn_ptr, g_xn);
    cudaGetSymbolAddress((void**)&u_ptr,  g_u);
    cudaGetSymbolAddress((void**)&y_ptr,  g_y);

    // 1. RMSNorm
    rmsnorm_kernel<<<NTOK, 256>>>(x, norm_w);

    // 2. u = xn @ W_in^T   (M=4096, N=6144, K=768)
    {
        dim3 grid(N_IN / 128, NTOK / 128);
        sgemm_nt<<<grid, 256>>>(xn_ptr, W_in, u_ptr, NTOK, N_IN, D_MODEL);
    }

    // 3. complex recurrence scan + rank sum -> y
    {
        int warps = BATCH * D_MODEL;              // 1536
        int blocks = (warps * 32 + 255) / 256;    // 192
        scan_kernel<<<blocks, 256>>>(a_p, b_p, c_p);
    }

    // 4. out = y @ W_out^T (M=4096, N=768, K=768)
    {
        dim3 grid(D_MODEL / 128, NTOK / 128);
        sgemm_nt<<<grid, 256>>>(y_ptr, W_out, out, NTOK, D_MODEL, D_MODEL);
    }
}

// round 3
// speedup vs baseline: 2.2546x; 2.2546x over previous
#include <cuda_runtime.h>
#include <cuda_bf16.h>
#include <cstdint>

#define D_MODEL 768
#define RANK    4
#define BATCH   2
#define T_LEN   2048
#define NTOK    (BATCH * T_LEN)        // 4096
#define N_IN    (D_MODEL * RANK * 2)   // 6144

// ---------------- scratch (device globals; allocation-free rule) ----------------
__device__ float          g_u    [(size_t)NTOK * N_IN];      // 100.7 MB fp32
__device__ __nv_bfloat16  g_xn_hi[(size_t)NTOK * D_MODEL];
__device__ __nv_bfloat16  g_xn_lo[(size_t)NTOK * D_MODEL];
__device__ __nv_bfloat16  g_y_hi [(size_t)NTOK * D_MODEL];
__device__ __nv_bfloat16  g_y_lo [(size_t)NTOK * D_MODEL];
__device__ __nv_bfloat16  g_wi_hi[(size_t)N_IN * D_MODEL];
__device__ __nv_bfloat16  g_wi_lo[(size_t)N_IN * D_MODEL];
__device__ __nv_bfloat16  g_wo_hi[(size_t)D_MODEL * D_MODEL];
__device__ __nv_bfloat16  g_wo_lo[(size_t)D_MODEL * D_MODEL];

// ---------------------------------------------------------------------------
// helpers
// ---------------------------------------------------------------------------
__device__ __forceinline__ void split_bf16(float v, __nv_bfloat16& h, __nv_bfloat16& l) {
    h = __float2bfloat16_rn(v);
    l = __float2bfloat16_rn(v - __bfloat162float(h));
}

__device__ __forceinline__ void ldsm_x4(uint32_t addr, uint32_t& r0, uint32_t& r1,
                                        uint32_t& r2, uint32_t& r3) {
    asm volatile("ldmatrix.sync.aligned.m8n8.x4.shared.b16 {%0,%1,%2,%3}, [%4];"
                 : "=r"(r0), "=r"(r1), "=r"(r2), "=r"(r3) : "r"(addr));
}

__device__ __forceinline__ void mma_bf16(float* c, const uint32_t* a, const uint32_t* b) {
    asm volatile(
        "mma.sync.aligned.m16n8k16.row.col.f32.bf16.bf16.f32 "
        "{%0,%1,%2,%3}, {%4,%5,%6,%7}, {%8,%9}, {%0,%1,%2,%3};"
        : "+f"(c[0]), "+f"(c[1]), "+f"(c[2]), "+f"(c[3])
        : "r"(a[0]), "r"(a[1]), "r"(a[2]), "r"(a[3]), "r"(b[0]), "r"(b[1]));
}

#define CP_ASYNC16(dst, src) \
    asm volatile("cp.async.cg.shared.global [%0], [%1], 16;" :: "r"(dst), "l"(src))

// ---------------------------------------------------------------------------
// weight split: fp32 -> (hi, lo) bf16.  n divisible by 1024.
// ---------------------------------------------------------------------------
__global__ __launch_bounds__(256) void split_kernel(const float* __restrict__ src,
                                                    __nv_bfloat16* __restrict__ hi,
                                                    __nv_bfloat16* __restrict__ lo) {
    int i = (blockIdx.x * 256 + threadIdx.x) * 4;
    float4 v = *(const float4*)(src + i);
    __nv_bfloat16 h0, l0, h1, l1, h2, l2, h3, l3;
    split_bf16(v.x, h0, l0); split_bf16(v.y, h1, l1);
    split_bf16(v.z, h2, l2); split_bf16(v.w, h3, l3);
    *(__nv_bfloat162*)(hi + i)     = __nv_bfloat162(h0, h1);
    *(__nv_bfloat162*)(hi + i + 2) = __nv_bfloat162(h2, h3);
    *(__nv_bfloat162*)(lo + i)     = __nv_bfloat162(l0, l1);
    *(__nv_bfloat162*)(lo + i + 2) = __nv_bfloat162(l2, l3);
}

// ---------------------------------------------------------------------------
// RMSNorm -> split bf16 hi/lo
// ---------------------------------------------------------------------------
__global__ __launch_bounds__(256) void rmsnorm_kernel(const float* __restrict__ x,
                                                      const float* __restrict__ w) {
    int tok = blockIdx.x;
    const float* xr = x + (size_t)tok * D_MODEL;
    int t = threadIdx.x;

    float v[3];
    float ss = 0.f;
#pragma unroll
    for (int i = 0; i < 3; i++) { v[i] = xr[t + 256 * i]; ss += v[i] * v[i]; }

    __shared__ float red[8];
#pragma unroll
    for (int off = 16; off; off >>= 1) ss += __shfl_down_sync(0xffffffffu, ss, off);
    if ((t & 31) == 0) red[t >> 5] = ss;
    __syncthreads();
    if (t < 8) {
        float s = red[t];
#pragma unroll
        for (int off = 4; off; off >>= 1) s += __shfl_down_sync(0xffu, s, off);
        if (t == 0) red[0] = s;
    }
    __syncthreads();
    float scale = rsqrtf(red[0] * (1.0f / D_MODEL) + 1e-6f);
#pragma unroll
    for (int i = 0; i < 3; i++) {
        int idx = tok * D_MODEL + t + 256 * i;
        __nv_bfloat16 h, l;
        split_bf16(v[i] * scale * w[t + 256 * i], h, l);
        g_xn_hi[idx] = h;
        g_xn_lo[idx] = l;
    }
}

// ---------------------------------------------------------------------------
// bf16x3 GEMM (NT): C[m,n] = sum_k A[m,k]*B[n,k],  A = Ahi+Alo, B = Bhi+Blo
// C += AhiBhi + AhiBlo + AloBhi  (fp32 accum)
// BM=128, BN=128, BK=32, 3-stage cp.async, 256 threads, warps 2(M)x4(N)
// smem tile row = 128B: chunks 0-3 = hi k0..31, 4-7 = lo k0..31, xor-swizzled
// ---------------------------------------------------------------------------
#define GBM 128
#define GBN 128
#define GBK 32
#define STAGE_BYTES (GBM * 128 + GBN * 128)   // A tile 16KB + B tile 16KB
#define NSTAGES 3

__global__ __launch_bounds__(256, 1) void gemm_bf16x3(
    const __nv_bfloat16* __restrict__ Ahi, const __nv_bfloat16* __restrict__ Alo,
    const __nv_bfloat16* __restrict__ Bhi, const __nv_bfloat16* __restrict__ Blo,
    float* __restrict__ C, int N, int K) {

    extern __shared__ char smem[];
    const uint32_t smem_u32 = (uint32_t)__cvta_generic_to_shared(smem);

    const int t    = threadIdx.x;
    const int lane = t & 31;
    const int wid  = t >> 5;
    const int wm   = wid & 1;        // 0..1 -> 64-row half
    const int wn   = wid >> 1;       // 0..3 -> 32-col quarter

    const int bm = blockIdx.y * GBM;
    const int bn = blockIdx.x * GBN;

    // loader mapping: c = chunk 0..7 (0-3 hi, 4-7 lo), 4 row passes of 32
    const int lc    = t & 7;
    const int lrow0 = t >> 3;             // 0..31
    const int lkoff = (lc & 3) * 8;
    const bool lhi  = lc < 4;

    float acc[4][4][4];
#pragma unroll
    for (int i = 0; i < 4; i++)
#pragma unroll
        for (int j = 0; j < 4; j++)
#pragma unroll
            for (int q = 0; q < 4; q++) acc[i][j][q] = 0.f;

    const int KI = K / GBK;

    auto load_stage = [&](int stage, int k0) {
        uint32_t sA = smem_u32 + stage * STAGE_BYTES;
        uint32_t sB = sA + GBM * 128;
#pragma unroll
        for (int p = 0; p < 4; p++) {
            int m = lrow0 + p * 32;
            const __nv_bfloat16* srcA = (lhi ? Ahi : Alo) + (size_t)(bm + m) * K + k0 + lkoff;
            CP_ASYNC16(sA + m * 128 + ((lc ^ (m & 7)) * 16), srcA);
        }
#pragma unroll
        for (int p = 0; p < 4; p++) {
            int n = lrow0 + p * 32;
            const __nv_bfloat16* srcB = (lhi ? Bhi : Blo) + (size_t)(bn + n) * K + k0 + lkoff;
            CP_ASYNC16(sB + n * 128 + ((lc ^ (n & 7)) * 16), srcB);
        }
    };

    load_stage(0, 0);
    asm volatile("cp.async.commit_group;" ::: "memory");
    load_stage(1, GBK);
    asm volatile("cp.async.commit_group;" ::: "memory");

    for (int it = 0; it < KI; ++it) {
        asm volatile("cp.async.wait_group 1;" ::: "memory");
        __syncthreads();

        int ldk = it + 2;
        if (ldk < KI) load_stage(ldk % NSTAGES, ldk * GBK);
        asm volatile("cp.async.commit_group;" ::: "memory");

        uint32_t sA = smem_u32 + (it % NSTAGES) * STAGE_BYTES;
        uint32_t sB = sA + GBM * 128;

#pragma unroll
        for (int kst = 0; kst < 2; kst++) {
            uint32_t afh[4][4], afl[4][4];
#pragma unroll
            for (int i = 0; i < 4; i++) {
                int row = wm * 64 + i * 16 + (lane & 15);
                int ch  = kst * 2 + (lane >> 4);        // hi chunk
                ldsm_x4(sA + row * 128 + ((ch ^ (row & 7)) * 16),
                        afh[i][0], afh[i][1], afh[i][2], afh[i][3]);
                int cl  = 4 + kst * 2 + (lane >> 4);    // lo chunk
                ldsm_x4(sA + row * 128 + ((cl ^ (row & 7)) * 16),
                        afl[i][0], afl[i][1], afl[i][2], afl[i][3]);
            }
            uint32_t bfh[4][2], bfl[4][2];
#pragma unroll
            for (int j = 0; j < 2; j++) {
                int row = wn * 32 + j * 16 + (lane & 7) + ((lane >> 4) << 3);
                int ch  = kst * 2 + ((lane >> 3) & 1);
                uint32_t r0, r1, r2, r3;
                ldsm_x4(sB + row * 128 + ((ch ^ (row & 7)) * 16), r0, r1, r2, r3);
                bfh[2 * j][0] = r0; bfh[2 * j][1] = r1;
                bfh[2 * j + 1][0] = r2; bfh[2 * j + 1][1] = r3;
                int cl  = 4 + kst * 2 + ((lane >> 3) & 1);
                ldsm_x4(sB + row * 128 + ((cl ^ (row & 7)) * 16), r0, r1, r2, r3);
                bfl[2 * j][0] = r0; bfl[2 * j][1] = r1;
                bfl[2 * j + 1][0] = r2; bfl[2 * j + 1][1] = r3;
            }
#pragma unroll
            for (int i = 0; i < 4; i++)
#pragma unroll
                for (int j = 0; j < 4; j++) {
                    mma_bf16(acc[i][j], afh[i], bfh[j]);
                    mma_bf16(acc[i][j], afh[i], bfl[j]);
                    mma_bf16(acc[i][j], afl[i], bfh[j]);
                }
        }
    }

    // epilogue
#pragma unroll
    for (int i = 0; i < 4; i++) {
        int m0 = bm + wm * 64 + i * 16 + (lane >> 2);
#pragma unroll
        for (int j = 0; j < 4; j++) {
            int n0 = bn + wn * 32 + j * 8 + (lane & 3) * 2;
            *(float2*)(C + (size_t)m0 * N + n0)       = make_float2(acc[i][j][0], acc[i][j][1]);
            *(float2*)(C + (size_t)(m0 + 8) * N + n0) = make_float2(acc[i][j][2], acc[i][j][3]);
        }
    }
}

// ---------------------------------------------------------------------------
// complex linear recurrence scan; emits y as bf16 hi/lo for GEMM2
// ---------------------------------------------------------------------------
__global__ __launch_bounds__(256) void scan_kernel(const float* __restrict__ a_p,
                                                   const float* __restrict__ b_p,
                                                   const float* __restrict__ c_p) {
    int warp = (blockIdx.x * blockDim.x + threadIdx.x) >> 5;
    int lane = threadIdx.x & 31;
    if (warp >= BATCH * D_MODEL) return;
    int b = warp / D_MODEL;
    int d = warp % D_MODEL;

    float ar[RANK], ai[RANK], br_[RANK], bi[RANK], cr[RANK], ci[RANK];
#pragma unroll
    for (int r = 0; r < RANK; r++) {
        int idx = (d * RANK + r) * 2;
        ar[r]  = tanhf(a_p[idx + 0]) * 0.97f;
        ai[r]  = tanhf(a_p[idx + 1]) * 0.97f;
        br_[r] = tanhf(b_p[idx + 0]);
        bi[r]  = tanhf(b_p[idx + 1]);
        cr[r]  = tanhf(c_p[idx + 0]);
        ci[r]  = tanhf(c_p[idx + 1]);
    }

    const int CH = T_LEN / 32;
    const size_t tstride = (size_t)D_MODEL * RANK * 2;
    const float* ub = g_u + (size_t)b * T_LEN * tstride + (size_t)d * RANK * 2;
    int t0 = lane * CH;

    float sr[RANK] = {0, 0, 0, 0}, si[RANK] = {0, 0, 0, 0};
    {
        const float* up = ub + (size_t)t0 * tstride;
        for (int i = 0; i < CH; i++) {
            float4 u0 = *(const float4*)(up);
            float4 u1 = *(const float4*)(up + 4);
            float ur[4] = {u0.x, u0.z, u1.x, u1.z};
            float ui[4] = {u0.y, u0.w, u1.y, u1.w};
#pragma unroll
            for (int r = 0; r < RANK; r++) {
                float nsr = ar[r] * sr[r] - ai[r] * si[r] + br_[r] * ur[r] - bi[r] * ui[r];
                float nsi = ar[r] * si[r] + ai[r] * sr[r] + br_[r] * ui[r] + bi[r] * ur[r];
                sr[r] = nsr; si[r] = nsi;
            }
            up += tstride;
        }
    }

    float Pr[RANK], Pi[RANK];
#pragma unroll
    for (int r = 0; r < RANK; r++) {
        float pr = ar[r], pi = ai[r];
#pragma unroll
        for (int s = 0; s < 6; s++) { float nr = pr * pr - pi * pi, ni = 2.f * pr * pi; pr = nr; pi = ni; }
        Pr[r] = pr; Pi[r] = pi;
    }

    for (int off = 1; off < 32; off <<= 1) {
#pragma unroll
        for (int r = 0; r < RANK; r++) {
            float prr = __shfl_up_sync(0xffffffffu, sr[r], off);
            float pri = __shfl_up_sync(0xffffffffu, si[r], off);
            if (lane >= off) {
                sr[r] += Pr[r] * prr - Pi[r] * pri;
                si[r] += Pr[r] * pri + Pi[r] * prr;
            }
        }
#pragma unroll
        for (int r = 0; r < RANK; r++) {
            float nr = Pr[r] * Pr[r] - Pi[r] * Pi[r];
            float ni = 2.f * Pr[r] * Pi[r];
            Pr[r] = nr; Pi[r] = ni;
        }
    }
#pragma unroll
    for (int r = 0; r < RANK; r++) {
        float prr = __shfl_up_sync(0xffffffffu, sr[r], 1);
        float pri = __shfl_up_sync(0xffffffffu, si[r], 1);
        sr[r] = (lane == 0) ? 0.f : prr;
        si[r] = (lane == 0) ? 0.f : pri;
    }

    {
        const float* up = ub + (size_t)t0 * tstride;
        size_t yi = (size_t)(b * T_LEN + t0) * D_MODEL + d;
        for (int i = 0; i < CH; i++) {
            float4 u0 = *(const float4*)(up);
            float4 u1 = *(const float4*)(up + 4);
            float ur[4] = {u0.x, u0.z, u1.x, u1.z};
            float ui[4] = {u0.y, u0.w, u1.y, u1.w};
            float y = 0.f;
#pragma unroll
            for (int r = 0; r < RANK; r++) {
                float nsr = ar[r] * sr[r] - ai[r] * si[r] + br_[r] * ur[r] - bi[r] * ui[r];
                float nsi = ar[r] * si[r] + ai[r] * sr[r] + br_[r] * ui[r] + bi[r] * ur[r];
                sr[r] = nsr; si[r] = nsi;
                y += cr[r] * nsr - ci[r] * nsi;
            }
            __nv_bfloat16 h, l;
            split_bf16(y, h, l);
            g_y_hi[yi] = h;
            g_y_lo[yi] = l;
            up += tstride;
            yi += D_MODEL;
        }
    }
}

// ---------------------------------------------------------------------------
extern "C" void kernel_launch(void* const* d_in, const int* in_sizes, int n_in,
                              void* d_out, int out_size) {
    const float* x      = (const float*)d_in[0];
    const float* norm_w = (const float*)d_in[1];
    const float* W_in   = (const float*)d_in[2];
    const float* W_out  = (const float*)d_in[3];
    const float* a_p    = (const float*)d_in[4];
    const float* b_p    = (const float*)d_in[5];
    const float* c_p    = (const float*)d_in[6];
    float* out = (float*)d_out;

    float* u_ptr;
    __nv_bfloat16 *xnh, *xnl, *yh, *yl, *wih, *wil, *woh, *wol;
    cudaGetSymbolAddress((void**)&u_ptr, g_u);
    cudaGetSymbolAddress((void**)&xnh, g_xn_hi);
    cudaGetSymbolAddress((void**)&xnl, g_xn_lo);
    cudaGetSymbolAddress((void**)&yh,  g_y_hi);
    cudaGetSymbolAddress((void**)&yl,  g_y_lo);
    cudaGetSymbolAddress((void**)&wih, g_wi_hi);
    cudaGetSymbolAddress((void**)&wil, g_wi_lo);
    cudaGetSymbolAddress((void**)&woh, g_wo_hi);
    cudaGetSymbolAddress((void**)&wol, g_wo_lo);

    static bool attr_set = false;
    if (!attr_set) {
        cudaFuncSetAttribute(gemm_bf16x3, cudaFuncAttributeMaxDynamicSharedMemorySize,
                             NSTAGES * STAGE_BYTES);
        attr_set = true;
    }

    // weight split (cheap; every call for determinism)
    split_kernel<<<(N_IN * D_MODEL) / 1024, 256>>>(W_in, wih, wil);
    split_kernel<<<(D_MODEL * D_MODEL) / 1024, 256>>>(W_out, woh, wol);

    // RMSNorm -> bf16 hi/lo
    rmsnorm_kernel<<<NTOK, 256>>>(x, norm_w);

    // u = xn @ W_in^T  (M=4096, N=6144, K=768)
    {
        dim3 grid(N_IN / GBN, NTOK / GBM);
        gemm_bf16x3<<<grid, 256, NSTAGES * STAGE_BYTES>>>(xnh, xnl, wih, wil,
                                                          u_ptr, N_IN, D_MODEL);
    }

    // scan -> y (bf16 hi/lo)
    {
        int warps = BATCH * D_MODEL;
        int blocks = (warps * 32 + 255) / 256;
        scan_kernel<<<blocks, 256>>>(a_p, b_p, c_p);
    }

    // out = y @ W_out^T (M=4096, N=768, K=768)
    {
        dim3 grid(D_MODEL / GBN, NTOK / GBM);
        gemm_bf16x3<<<grid, 256, NSTAGES * STAGE_BYTES>>>(yh, yl, woh, wol,
                                                          out, D_MODEL, D_MODEL);
    }
}

// round 8
// speedup vs baseline: 2.3217x; 1.0297x over previous
#include <cuda_runtime.h>
#include <cuda_bf16.h>
#include <cstdint>

#define D_MODEL 768
#define RANK    4
#define BATCH   2
#define T_LEN   2048
#define NTOK    (BATCH * T_LEN)        // 4096
#define N_IN    (D_MODEL * RANK * 2)   // 6144

// ---------------- scratch (device globals; allocation-free rule) ----------------
__device__ float          g_u    [(size_t)NTOK * N_IN];      // 100.7 MB fp32
__device__ __nv_bfloat16  g_xn_hi[(size_t)NTOK * D_MODEL];
__device__ __nv_bfloat16  g_xn_lo[(size_t)NTOK * D_MODEL];
__device__ __nv_bfloat16  g_y_hi [(size_t)NTOK * D_MODEL];
__device__ __nv_bfloat16  g_y_lo [(size_t)NTOK * D_MODEL];
__device__ __nv_bfloat16  g_wi_hi[(size_t)N_IN * D_MODEL];
__device__ __nv_bfloat16  g_wi_lo[(size_t)N_IN * D_MODEL];
__device__ __nv_bfloat16  g_wo_hi[(size_t)D_MODEL * D_MODEL];
__device__ __nv_bfloat16  g_wo_lo[(size_t)D_MODEL * D_MODEL];

// ---------------------------------------------------------------------------
// helpers
// ---------------------------------------------------------------------------
__device__ __forceinline__ void split_bf16(float v, __nv_bfloat16& h, __nv_bfloat16& l) {
    h = __float2bfloat16_rn(v);
    l = __float2bfloat16_rn(v - __bfloat162float(h));
}

__device__ __forceinline__ void ldsm_x4(uint32_t addr, uint32_t& r0, uint32_t& r1,
                                        uint32_t& r2, uint32_t& r3) {
    asm volatile("ldmatrix.sync.aligned.m8n8.x4.shared.b16 {%0,%1,%2,%3}, [%4];"
                 : "=r"(r0), "=r"(r1), "=r"(r2), "=r"(r3) : "r"(addr));
}

__device__ __forceinline__ void mma_bf16(float* c, const uint32_t* a, const uint32_t* b) {
    asm volatile(
        "mma.sync.aligned.m16n8k16.row.col.f32.bf16.bf16.f32 "
        "{%0,%1,%2,%3}, {%4,%5,%6,%7}, {%8,%9}, {%0,%1,%2,%3};"
        : "+f"(c[0]), "+f"(c[1]), "+f"(c[2]), "+f"(c[3])
        : "r"(a[0]), "r"(a[1]), "r"(a[2]), "r"(a[3]), "r"(b[0]), "r"(b[1]));
}

#define CP_ASYNC16(dst, src) \
    asm volatile("cp.async.cg.shared.global [%0], [%1], 16;" :: "r"(dst), "l"(src))

// ---------------------------------------------------------------------------
// weight split: fp32 -> (hi, lo) bf16.  n divisible by 1024.
// ---------------------------------------------------------------------------
__global__ __launch_bounds__(256) void split_kernel(const float* __restrict__ src,
                                                    __nv_bfloat16* __restrict__ hi,
                                                    __nv_bfloat16* __restrict__ lo) {
    int i = (blockIdx.x * 256 + threadIdx.x) * 4;
    float4 v = *(const float4*)(src + i);
    __nv_bfloat16 h0, l0, h1, l1, h2, l2, h3, l3;
    split_bf16(v.x, h0, l0); split_bf16(v.y, h1, l1);
    split_bf16(v.z, h2, l2); split_bf16(v.w, h3, l3);
    *(__nv_bfloat162*)(hi + i)     = __nv_bfloat162(h0, h1);
    *(__nv_bfloat162*)(hi + i + 2) = __nv_bfloat162(h2, h3);
    *(__nv_bfloat162*)(lo + i)     = __nv_bfloat162(l0, l1);
    *(__nv_bfloat162*)(lo + i + 2) = __nv_bfloat162(l2, l3);
}

// ---------------------------------------------------------------------------
// RMSNorm -> split bf16 hi/lo
// ---------------------------------------------------------------------------
__global__ __launch_bounds__(256) void rmsnorm_kernel(const float* __restrict__ x,
                                                      const float* __restrict__ w) {
    int tok = blockIdx.x;
    const float* xr = x + (size_t)tok * D_MODEL;
    int t = threadIdx.x;

    float v[3];
    float ss = 0.f;
#pragma unroll
    for (int i = 0; i < 3; i++) { v[i] = xr[t + 256 * i]; ss += v[i] * v[i]; }

    __shared__ float red[8];
#pragma unroll
    for (int off = 16; off; off >>= 1) ss += __shfl_down_sync(0xffffffffu, ss, off);
    if ((t & 31) == 0) red[t >> 5] = ss;
    __syncthreads();
    if (t < 8) {
        float s = red[t];
#pragma unroll
        for (int off = 4; off; off >>= 1) s += __shfl_down_sync(0xffu, s, off);
        if (t == 0) red[0] = s;
    }
    __syncthreads();
    float scale = rsqrtf(red[0] * (1.0f / D_MODEL) + 1e-6f);
#pragma unroll
    for (int i = 0; i < 3; i++) {
        int idx = tok * D_MODEL + t + 256 * i;
        __nv_bfloat16 h, l;
        split_bf16(v[i] * scale * w[t + 256 * i], h, l);
        g_xn_hi[idx] = h;
        g_xn_lo[idx] = l;
    }
}

// ---------------------------------------------------------------------------
// bf16x3 GEMM (NT): C[m,n] = sum_k A[m,k]*B[n,k],  A = Ahi+Alo, B = Bhi+Blo
// C += AhiBhi + AhiBlo + AloBhi  (fp32 accum)
// BM=128, BN=128, BK=32, 3-stage cp.async, 256 threads, warps 2(M)x4(N)
// __launch_bounds__(256,2): cap regs at 128 -> 2 CTAs/SM (16 warps, 4/SMSP)
// smem tile row = 128B: chunks 0-3 = hi k0..31, 4-7 = lo k0..31, xor-swizzled
// ---------------------------------------------------------------------------
#define GBM 128
#define GBN 128
#define GBK 32
#define STAGE_BYTES (GBM * 128 + GBN * 128)   // A tile 16KB + B tile 16KB
#define NSTAGES 3

__global__ __launch_bounds__(256, 2) void gemm_bf16x3(
    const __nv_bfloat16* __restrict__ Ahi, const __nv_bfloat16* __restrict__ Alo,
    const __nv_bfloat16* __restrict__ Bhi, const __nv_bfloat16* __restrict__ Blo,
    float* __restrict__ C, int N, int K) {

    extern __shared__ char smem[];
    const uint32_t smem_u32 = (uint32_t)__cvta_generic_to_shared(smem);

    const int t    = threadIdx.x;
    const int lane = t & 31;
    const int wid  = t >> 5;
    const int wm   = wid & 1;        // 0..1 -> 64-row half
    const int wn   = wid >> 1;       // 0..3 -> 32-col quarter

    const int bm = blockIdx.y * GBM;
    const int bn = blockIdx.x * GBN;

    // loader mapping: c = chunk 0..7 (0-3 hi, 4-7 lo), 4 row passes of 32
    const int lc    = t & 7;
    const int lrow0 = t >> 3;             // 0..31
    const int lkoff = (lc & 3) * 8;
    const bool lhi  = lc < 4;

    float acc[4][4][4];
#pragma unroll
    for (int i = 0; i < 4; i++)
#pragma unroll
        for (int j = 0; j < 4; j++)
#pragma unroll
            for (int q = 0; q < 4; q++) acc[i][j][q] = 0.f;

    const int KI = K / GBK;

    auto load_stage = [&](int stage, int k0) {
        uint32_t sA = smem_u32 + stage * STAGE_BYTES;
        uint32_t sB = sA + GBM * 128;
#pragma unroll
        for (int p = 0; p < 4; p++) {
            int m = lrow0 + p * 32;
            const __nv_bfloat16* srcA = (lhi ? Ahi : Alo) + (size_t)(bm + m) * K + k0 + lkoff;
            CP_ASYNC16(sA + m * 128 + ((lc ^ (m & 7)) * 16), srcA);
        }
#pragma unroll
        for (int p = 0; p < 4; p++) {
            int n = lrow0 + p * 32;
            const __nv_bfloat16* srcB = (lhi ? Bhi : Blo) + (size_t)(bn + n) * K + k0 + lkoff;
            CP_ASYNC16(sB + n * 128 + ((lc ^ (n & 7)) * 16), srcB);
        }
    };

    load_stage(0, 0);
    asm volatile("cp.async.commit_group;" ::: "memory");
    load_stage(1, GBK);
    asm volatile("cp.async.commit_group;" ::: "memory");

    for (int it = 0; it < KI; ++it) {
        asm volatile("cp.async.wait_group 1;" ::: "memory");
        __syncthreads();

        int ldk = it + 2;
        if (ldk < KI) load_stage(ldk % NSTAGES, ldk * GBK);
        asm volatile("cp.async.commit_group;" ::: "memory");

        uint32_t sA = smem_u32 + (it % NSTAGES) * STAGE_BYTES;
        uint32_t sB = sA + GBM * 128;

#pragma unroll
        for (int kst = 0; kst < 2; kst++) {
            uint32_t afh[4][4], afl[4][4];
#pragma unroll
            for (int i = 0; i < 4; i++) {
                int row = wm * 64 + i * 16 + (lane & 15);
                int ch  = kst * 2 + (lane >> 4);        // hi chunk
                ldsm_x4(sA + row * 128 + ((ch ^ (row & 7)) * 16),
                        afh[i][0], afh[i][1], afh[i][2], afh[i][3]);
                int cl  = 4 + kst * 2 + (lane >> 4);    // lo chunk
                ldsm_x4(sA + row * 128 + ((cl ^ (row & 7)) * 16),
                        afl[i][0], afl[i][1], afl[i][2], afl[i][3]);
            }
            uint32_t bfh[4][2], bfl[4][2];
#pragma unroll
            for (int j = 0; j < 2; j++) {
                int row = wn * 32 + j * 16 + (lane & 7) + ((lane >> 4) << 3);
                int ch  = kst * 2 + ((lane >> 3) & 1);
                uint32_t r0, r1, r2, r3;
                ldsm_x4(sB + row * 128 + ((ch ^ (row & 7)) * 16), r0, r1, r2, r3);
                bfh[2 * j][0] = r0; bfh[2 * j][1] = r1;
                bfh[2 * j + 1][0] = r2; bfh[2 * j + 1][1] = r3;
                int cl  = 4 + kst * 2 + ((lane >> 3) & 1);
                ldsm_x4(sB + row * 128 + ((cl ^ (row & 7)) * 16), r0, r1, r2, r3);
                bfl[2 * j][0] = r0; bfl[2 * j][1] = r1;
                bfl[2 * j + 1][0] = r2; bfl[2 * j + 1][1] = r3;
            }
#pragma unroll
            for (int i = 0; i < 4; i++)
#pragma unroll
                for (int j = 0; j < 4; j++) {
                    mma_bf16(acc[i][j], afh[i], bfh[j]);
                    mma_bf16(acc[i][j], afh[i], bfl[j]);
                    mma_bf16(acc[i][j], afl[i], bfh[j]);
                }
        }
    }

    // epilogue
#pragma unroll
    for (int i = 0; i < 4; i++) {
        int m0 = bm + wm * 64 + i * 16 + (lane >> 2);
#pragma unroll
        for (int j = 0; j < 4; j++) {
            int n0 = bn + wn * 32 + j * 8 + (lane & 3) * 2;
            *(float2*)(C + (size_t)m0 * N + n0)       = make_float2(acc[i][j][0], acc[i][j][1]);
            *(float2*)(C + (size_t)(m0 + 8) * N + n0) = make_float2(acc[i][j][2], acc[i][j][3]);
        }
    }
}

// ---------------------------------------------------------------------------
// complex linear recurrence scan; emits y as bf16 hi/lo for GEMM2
// ---------------------------------------------------------------------------
__global__ __launch_bounds__(256) void scan_kernel(const float* __restrict__ a_p,
                                                   const float* __restrict__ b_p,
                                                   const float* __restrict__ c_p) {
    int warp = (blockIdx.x * blockDim.x + threadIdx.x) >> 5;
    int lane = threadIdx.x & 31;
    if (warp >= BATCH * D_MODEL) return;
    int b = warp / D_MODEL;
    int d = warp % D_MODEL;

    float ar[RANK], ai[RANK], br_[RANK], bi[RANK], cr[RANK], ci[RANK];
#pragma unroll
    for (int r = 0; r < RANK; r++) {
        int idx = (d * RANK + r) * 2;
        ar[r]  = tanhf(a_p[idx + 0]) * 0.97f;
        ai[r]  = tanhf(a_p[idx + 1]) * 0.97f;
        br_[r] = tanhf(b_p[idx + 0]);
        bi[r]  = tanhf(b_p[idx + 1]);
        cr[r]  = tanhf(c_p[idx + 0]);
        ci[r]  = tanhf(c_p[idx + 1]);
    }

    const int CH = T_LEN / 32;
    const size_t tstride = (size_t)D_MODEL * RANK * 2;
    const float* ub = g_u + (size_t)b * T_LEN * tstride + (size_t)d * RANK * 2;
    int t0 = lane * CH;

    float sr[RANK] = {0, 0, 0, 0}, si[RANK] = {0, 0, 0, 0};
    {
        const float* up = ub + (size_t)t0 * tstride;
        for (int i = 0; i < CH; i++) {
            float4 u0 = *(const float4*)(up);
            float4 u1 = *(const float4*)(up + 4);
            float ur[4] = {u0.x, u0.z, u1.x, u1.z};
            float ui[4] = {u0.y, u0.w, u1.y, u1.w};
#pragma unroll
            for (int r = 0; r < RANK; r++) {
                float nsr = ar[r] * sr[r] - ai[r] * si[r] + br_[r] * ur[r] - bi[r] * ui[r];
                float nsi = ar[r] * si[r] + ai[r] * sr[r] + br_[r] * ui[r] + bi[r] * ur[r];
                sr[r] = nsr; si[r] = nsi;
            }
            up += tstride;
        }
    }

    float Pr[RANK], Pi[RANK];
#pragma unroll
    for (int r = 0; r < RANK; r++) {
        float pr = ar[r], pi = ai[r];
#pragma unroll
        for (int s = 0; s < 6; s++) { float nr = pr * pr - pi * pi, ni = 2.f * pr * pi; pr = nr; pi = ni; }
        Pr[r] = pr; Pi[r] = pi;
    }

    for (int off = 1; off < 32; off <<= 1) {
#pragma unroll
        for (int r = 0; r < RANK; r++) {
            float prr = __shfl_up_sync(0xffffffffu, sr[r], off);
            float pri = __shfl_up_sync(0xffffffffu, si[r], off);
            if (lane >= off) {
                sr[r] += Pr[r] * prr - Pi[r] * pri;
                si[r] += Pr[r] * pri + Pi[r] * prr;
            }
        }
#pragma unroll
        for (int r = 0; r < RANK; r++) {
            float nr = Pr[r] * Pr[r] - Pi[r] * Pi[r];
            float ni = 2.f * Pr[r] * Pi[r];
            Pr[r] = nr; Pi[r] = ni;
        }
    }
#pragma unroll
    for (int r = 0; r < RANK; r++) {
        float prr = __shfl_up_sync(0xffffffffu, sr[r], 1);
        float pri = __shfl_up_sync(0xffffffffu, si[r], 1);
        sr[r] = (lane == 0) ? 0.f : prr;
        si[r] = (lane == 0) ? 0.f : pri;
    }

    {
        const float* up = ub + (size_t)t0 * tstride;
        size_t yi = (size_t)(b * T_LEN + t0) * D_MODEL + d;
        for (int i = 0; i < CH; i++) {
            float4 u0 = *(const float4*)(up);
            float4 u1 = *(const float4*)(up + 4);
            float ur[4] = {u0.x, u0.z, u1.x, u1.z};
            float ui[4] = {u0.y, u0.w, u1.y, u1.w};
            float y = 0.f;
#pragma unroll
            for (int r = 0; r < RANK; r++) {
                float nsr = ar[r] * sr[r] - ai[r] * si[r] + br_[r] * ur[r] - bi[r] * ui[r];
                float nsi = ar[r] * si[r] + ai[r] * sr[r] + br_[r] * ui[r] + bi[r] * ur[r];
                sr[r] = nsr; si[r] = nsi;
                y += cr[r] * nsr - ci[r] * nsi;
            }
            __nv_bfloat16 h, l;
            split_bf16(y, h, l);
            g_y_hi[yi] = h;
            g_y_lo[yi] = l;
            up += tstride;
            yi += D_MODEL;
        }
    }
}

// ---------------------------------------------------------------------------
extern "C" void kernel_launch(void* const* d_in, const int* in_sizes, int n_in,
                              void* d_out, int out_size) {
    const float* x      = (const float*)d_in[0];
    const float* norm_w = (const float*)d_in[1];
    const float* W_in   = (const float*)d_in[2];
    const float* W_out  = (const float*)d_in[3];
    const float* a_p    = (const float*)d_in[4];
    const float* b_p    = (const float*)d_in[5];
    const float* c_p    = (const float*)d_in[6];
    float* out = (float*)d_out;

    float* u_ptr;
    __nv_bfloat16 *xnh, *xnl, *yh, *yl, *wih, *wil, *woh, *wol;
    cudaGetSymbolAddress((void**)&u_ptr, g_u);
    cudaGetSymbolAddress((void**)&xnh, g_xn_hi);
    cudaGetSymbolAddress((void**)&xnl, g_xn_lo);
    cudaGetSymbolAddress((void**)&yh,  g_y_hi);
    cudaGetSymbolAddress((void**)&yl,  g_y_lo);
    cudaGetSymbolAddress((void**)&wih, g_wi_hi);
    cudaGetSymbolAddress((void**)&wil, g_wi_lo);
    cudaGetSymbolAddress((void**)&woh, g_wo_hi);
    cudaGetSymbolAddress((void**)&wol, g_wo_lo);

    static bool attr_set = false;
    if (!attr_set) {
        cudaFuncSetAttribute(gemm_bf16x3, cudaFuncAttributeMaxDynamicSharedMemorySize,
                             NSTAGES * STAGE_BYTES);
        attr_set = true;
    }

    // weight split (cheap; every call for determinism)
    split_kernel<<<(N_IN * D_MODEL) / 1024, 256>>>(W_in, wih, wil);
    split_kernel<<<(D_MODEL * D_MODEL) / 1024, 256>>>(W_out, woh, wol);

    // RMSNorm -> bf16 hi/lo
    rmsnorm_kernel<<<NTOK, 256>>>(x, norm_w);

    // u = xn @ W_in^T  (M=4096, N=6144, K=768)
    {
        dim3 grid(N_IN / GBN, NTOK / GBM);
        gemm_bf16x3<<<grid, 256, NSTAGES * STAGE_BYTES>>>(xnh, xnl, wih, wil,
                                                          u_ptr, N_IN, D_MODEL);
    }

    // scan -> y (bf16 hi/lo)
    {
        int warps = BATCH * D_MODEL;
        int blocks = (warps * 32 + 255) / 256;
        scan_kernel<<<blocks, 256>>>(a_p, b_p, c_p);
    }

    // out = y @ W_out^T (M=4096, N=768, K=768)
    {
        dim3 grid(D_MODEL / GBN, NTOK / GBM);
        gemm_bf16x3<<<grid, 256, NSTAGES * STAGE_BYTES>>>(yh, yl, woh, wol,
                                                          out, D_MODEL, D_MODEL);
    }
}

// round 9
// speedup vs baseline: 2.9175x; 1.2566x over previous
#include <cuda_runtime.h>
#include <cuda_bf16.h>
#include <cuda_fp16.h>
#include <cstdint>

#define D_MODEL 768
#define RANK    4
#define BATCH   2
#define T_LEN   2048
#define NTOK    (BATCH * T_LEN)        // 4096
#define N_IN    (D_MODEL * RANK * 2)   // 6144

// ---------------- scratch (device globals; allocation-free rule) ----------------
__device__ float          g_u    [(size_t)NTOK * N_IN];      // 100.7 MB fp32
__device__ __half         g_xn_hi[(size_t)NTOK * D_MODEL];   // fp16 hi
__device__ __half         g_xn_lo[(size_t)NTOK * D_MODEL];   // fp16 lo
__device__ __nv_bfloat16  g_y_hi [(size_t)NTOK * D_MODEL];
__device__ __nv_bfloat16  g_y_lo [(size_t)NTOK * D_MODEL];
__device__ __half         g_wi_h [(size_t)N_IN * D_MODEL];   // W_in in fp16 (single)
__device__ __nv_bfloat16  g_wo_hi[(size_t)D_MODEL * D_MODEL];
__device__ __nv_bfloat16  g_wo_lo[(size_t)D_MODEL * D_MODEL];

// ---------------------------------------------------------------------------
// helpers
// ---------------------------------------------------------------------------
__device__ __forceinline__ void split_bf16(float v, __nv_bfloat16& h, __nv_bfloat16& l) {
    h = __float2bfloat16_rn(v);
    l = __float2bfloat16_rn(v - __bfloat162float(h));
}

__device__ __forceinline__ void split_f16(float v, __half& h, __half& l) {
    h = __float2half_rn(v);
    l = __float2half_rn(v - __half2float(h));
}

__device__ __forceinline__ void ldsm_x4(uint32_t addr, uint32_t& r0, uint32_t& r1,
                                        uint32_t& r2, uint32_t& r3) {
    asm volatile("ldmatrix.sync.aligned.m8n8.x4.shared.b16 {%0,%1,%2,%3}, [%4];"
                 : "=r"(r0), "=r"(r1), "=r"(r2), "=r"(r3) : "r"(addr));
}

__device__ __forceinline__ void mma_bf16(float* c, const uint32_t* a, const uint32_t* b) {
    asm volatile(
        "mma.sync.aligned.m16n8k16.row.col.f32.bf16.bf16.f32 "
        "{%0,%1,%2,%3}, {%4,%5,%6,%7}, {%8,%9}, {%0,%1,%2,%3};"
        : "+f"(c[0]), "+f"(c[1]), "+f"(c[2]), "+f"(c[3])
        : "r"(a[0]), "r"(a[1]), "r"(a[2]), "r"(a[3]), "r"(b[0]), "r"(b[1]));
}

__device__ __forceinline__ void mma_f16(float* c, const uint32_t* a, const uint32_t* b) {
    asm volatile(
        "mma.sync.aligned.m16n8k16.row.col.f32.f16.f16.f32 "
        "{%0,%1,%2,%3}, {%4,%5,%6,%7}, {%8,%9}, {%0,%1,%2,%3};"
        : "+f"(c[0]), "+f"(c[1]), "+f"(c[2]), "+f"(c[3])
        : "r"(a[0]), "r"(a[1]), "r"(a[2]), "r"(a[3]), "r"(b[0]), "r"(b[1]));
}

#define CP_ASYNC16(dst, src) \
    asm volatile("cp.async.cg.shared.global [%0], [%1], 16;" :: "r"(dst), "l"(src))

// B-tile swizzle for 64B rows: 4 chunks of 16B, conflict-free over 8-row ldsm groups
#define BSWZ(row, c) (((c) ^ ((row) & 3) ^ (((row) >> 2) & 3)))

// ---------------------------------------------------------------------------
// weight split kernels
// ---------------------------------------------------------------------------
__global__ __launch_bounds__(256) void split_kernel_bf16(const float* __restrict__ src,
                                                         __nv_bfloat16* __restrict__ hi,
                                                         __nv_bfloat16* __restrict__ lo) {
    int i = (blockIdx.x * 256 + threadIdx.x) * 4;
    float4 v = *(const float4*)(src + i);
    __nv_bfloat16 h0, l0, h1, l1, h2, l2, h3, l3;
    split_bf16(v.x, h0, l0); split_bf16(v.y, h1, l1);
    split_bf16(v.z, h2, l2); split_bf16(v.w, h3, l3);
    *(__nv_bfloat162*)(hi + i)     = __nv_bfloat162(h0, h1);
    *(__nv_bfloat162*)(hi + i + 2) = __nv_bfloat162(h2, h3);
    *(__nv_bfloat162*)(lo + i)     = __nv_bfloat162(l0, l1);
    *(__nv_bfloat162*)(lo + i + 2) = __nv_bfloat162(l2, l3);
}

__global__ __launch_bounds__(256) void round_kernel_f16(const float* __restrict__ src,
                                                        __half* __restrict__ dst) {
    int i = (blockIdx.x * 256 + threadIdx.x) * 4;
    float4 v = *(const float4*)(src + i);
    __half2 p0 = __half2(__float2half_rn(v.x), __float2half_rn(v.y));
    __half2 p1 = __half2(__float2half_rn(v.z), __float2half_rn(v.w));
    *(__half2*)(dst + i)     = p0;
    *(__half2*)(dst + i + 2) = p1;
}

// ---------------------------------------------------------------------------
// RMSNorm -> split fp16 hi/lo
// ---------------------------------------------------------------------------
__global__ __launch_bounds__(256) void rmsnorm_kernel(const float* __restrict__ x,
                                                      const float* __restrict__ w) {
    int tok = blockIdx.x;
    const float* xr = x + (size_t)tok * D_MODEL;
    int t = threadIdx.x;

    float v[3];
    float ss = 0.f;
#pragma unroll
    for (int i = 0; i < 3; i++) { v[i] = xr[t + 256 * i]; ss += v[i] * v[i]; }

    __shared__ float red[8];
#pragma unroll
    for (int off = 16; off; off >>= 1) ss += __shfl_down_sync(0xffffffffu, ss, off);
    if ((t & 31) == 0) red[t >> 5] = ss;
    __syncthreads();
    if (t < 8) {
        float s = red[t];
#pragma unroll
        for (int off = 4; off; off >>= 1) s += __shfl_down_sync(0xffu, s, off);
        if (t == 0) red[0] = s;
    }
    __syncthreads();
    float scale = rsqrtf(red[0] * (1.0f / D_MODEL) + 1e-6f);
#pragma unroll
    for (int i = 0; i < 3; i++) {
        int idx = tok * D_MODEL + t + 256 * i;
        __half h, l;
        split_f16(v[i] * scale * w[t + 256 * i], h, l);
        g_xn_hi[idx] = h;
        g_xn_lo[idx] = l;
    }
}

// ---------------------------------------------------------------------------
// fp16x2 GEMM (NT): C[m,n] = sum_k (Ahi+Alo)[m,k] * B[n,k]   (2 MMA terms)
// A hi/lo fp16, B single fp16. BM=128, BN=128, BK=32, 3-stage cp.async.
// A smem row: 128B = hi chunks 0-3 (k0..31) + lo chunks 4-7, xor(&7) swizzle.
// B smem row: 64B = chunks 0-3 (k0..31), BSWZ swizzle.
// ---------------------------------------------------------------------------
#define GBM 128
#define GBN 128
#define GBK 32
#define F16_A_BYTES (GBM * 128)
#define F16_B_BYTES (GBN * 64)
#define F16_STAGE   (F16_A_BYTES + F16_B_BYTES)      // 24576
#define NSTAGES 3

__global__ __launch_bounds__(256, 2) void gemm_f16x2(
    const __half* __restrict__ Ahi, const __half* __restrict__ Alo,
    const __half* __restrict__ Bh,
    float* __restrict__ C, int N, int K) {

    extern __shared__ char smem[];
    const uint32_t smem_u32 = (uint32_t)__cvta_generic_to_shared(smem);

    const int t    = threadIdx.x;
    const int lane = t & 31;
    const int wid  = t >> 5;
    const int wm   = wid & 1;
    const int wn   = wid >> 1;

    const int bm = blockIdx.y * GBM;
    const int bn = blockIdx.x * GBN;

    const int alc   = t & 7;          // A chunk (0-3 hi, 4-7 lo)
    const int arow0 = t >> 3;         // 0..31
    const int akoff = (alc & 3) * 8;
    const bool ahi  = alc < 4;
    const int blc   = t & 3;          // B chunk
    const int brow0 = t >> 2;         // 0..63
    const int bkoff = blc * 8;

    float acc[4][4][4];
#pragma unroll
    for (int i = 0; i < 4; i++)
#pragma unroll
        for (int j = 0; j < 4; j++)
#pragma unroll
            for (int q = 0; q < 4; q++) acc[i][j][q] = 0.f;

    const int KI = K / GBK;

    auto load_stage = [&](int stage, int k0) {
        uint32_t sA = smem_u32 + stage * F16_STAGE;
        uint32_t sB = sA + F16_A_BYTES;
#pragma unroll
        for (int p = 0; p < 4; p++) {
            int m = arow0 + p * 32;
            const __half* srcA = (ahi ? Ahi : Alo) + (size_t)(bm + m) * K + k0 + akoff;
            CP_ASYNC16(sA + m * 128 + ((alc ^ (m & 7)) * 16), srcA);
        }
#pragma unroll
        for (int p = 0; p < 2; p++) {
            int n = brow0 + p * 64;
            const __half* srcB = Bh + (size_t)(bn + n) * K + k0 + bkoff;
            CP_ASYNC16(sB + n * 64 + (BSWZ(n, blc) * 16), srcB);
        }
    };

    load_stage(0, 0);
    asm volatile("cp.async.commit_group;" ::: "memory");
    load_stage(1, GBK);
    asm volatile("cp.async.commit_group;" ::: "memory");

    for (int it = 0; it < KI; ++it) {
        asm volatile("cp.async.wait_group 1;" ::: "memory");
        __syncthreads();

        int ldk = it + 2;
        if (ldk < KI) load_stage(ldk % NSTAGES, ldk * GBK);
        asm volatile("cp.async.commit_group;" ::: "memory");

        uint32_t sA = smem_u32 + (it % NSTAGES) * F16_STAGE;
        uint32_t sB = sA + F16_A_BYTES;

#pragma unroll
        for (int kst = 0; kst < 2; kst++) {
            uint32_t afh[4][4], afl[4][4];
#pragma unroll
            for (int i = 0; i < 4; i++) {
                int row = wm * 64 + i * 16 + (lane & 15);
                int ch  = kst * 2 + (lane >> 4);
                ldsm_x4(sA + row * 128 + ((ch ^ (row & 7)) * 16),
                        afh[i][0], afh[i][1], afh[i][2], afh[i][3]);
                int cl  = 4 + kst * 2 + (lane >> 4);
                ldsm_x4(sA + row * 128 + ((cl ^ (row & 7)) * 16),
                        afl[i][0], afl[i][1], afl[i][2], afl[i][3]);
            }
            uint32_t bf[4][2];
#pragma unroll
            for (int j = 0; j < 2; j++) {
                int row = wn * 32 + j * 16 + (lane & 7) + ((lane >> 4) << 3);
                int ch  = kst * 2 + ((lane >> 3) & 1);
                uint32_t r0, r1, r2, r3;
                ldsm_x4(sB + row * 64 + (BSWZ(row, ch) * 16), r0, r1, r2, r3);
                bf[2 * j][0] = r0; bf[2 * j][1] = r1;
                bf[2 * j + 1][0] = r2; bf[2 * j + 1][1] = r3;
            }
#pragma unroll
            for (int i = 0; i < 4; i++)
#pragma unroll
                for (int j = 0; j < 4; j++) {
                    mma_f16(acc[i][j], afh[i], bf[j]);
                    mma_f16(acc[i][j], afl[i], bf[j]);
                }
        }
    }

#pragma unroll
    for (int i = 0; i < 4; i++) {
        int m0 = bm + wm * 64 + i * 16 + (lane >> 2);
#pragma unroll
        for (int j = 0; j < 4; j++) {
            int n0 = bn + wn * 32 + j * 8 + (lane & 3) * 2;
            *(float2*)(C + (size_t)m0 * N + n0)       = make_float2(acc[i][j][0], acc[i][j][1]);
            *(float2*)(C + (size_t)(m0 + 8) * N + n0) = make_float2(acc[i][j][2], acc[i][j][3]);
        }
    }
}

// ---------------------------------------------------------------------------
// bf16x3 GEMM (NT) — unchanged proven path, used for out-proj
// ---------------------------------------------------------------------------
#define BSTAGE_BYTES (GBM * 128 + GBN * 128)

__global__ __launch_bounds__(256, 2) void gemm_bf16x3(
    const __nv_bfloat16* __restrict__ Ahi, const __nv_bfloat16* __restrict__ Alo,
    const __nv_bfloat16* __restrict__ Bhi, const __nv_bfloat16* __restrict__ Blo,
    float* __restrict__ C, int N, int K) {

    extern __shared__ char smem[];
    const uint32_t smem_u32 = (uint32_t)__cvta_generic_to_shared(smem);

    const int t    = threadIdx.x;
    const int lane = t & 31;
    const int wid  = t >> 5;
    const int wm   = wid & 1;
    const int wn   = wid >> 1;

    const int bm = blockIdx.y * GBM;
    const int bn = blockIdx.x * GBN;

    const int lc    = t & 7;
    const int lrow0 = t >> 3;
    const int lkoff = (lc & 3) * 8;
    const bool lhi  = lc < 4;

    float acc[4][4][4];
#pragma unroll
    for (int i = 0; i < 4; i++)
#pragma unroll
        for (int j = 0; j < 4; j++)
#pragma unroll
            for (int q = 0; q < 4; q++) acc[i][j][q] = 0.f;

    const int KI = K / GBK;

    auto load_stage = [&](int stage, int k0) {
        uint32_t sA = smem_u32 + stage * BSTAGE_BYTES;
        uint32_t sB = sA + GBM * 128;
#pragma unroll
        for (int p = 0; p < 4; p++) {
            int m = lrow0 + p * 32;
            const __nv_bfloat16* srcA = (lhi ? Ahi : Alo) + (size_t)(bm + m) * K + k0 + lkoff;
            CP_ASYNC16(sA + m * 128 + ((lc ^ (m & 7)) * 16), srcA);
        }
#pragma unroll
        for (int p = 0; p < 4; p++) {
            int n = lrow0 + p * 32;
            const __nv_bfloat16* srcB = (lhi ? Bhi : Blo) + (size_t)(bn + n) * K + k0 + lkoff;
            CP_ASYNC16(sB + n * 128 + ((lc ^ (n & 7)) * 16), srcB);
        }
    };

    load_stage(0, 0);
    asm volatile("cp.async.commit_group;" ::: "memory");
    load_stage(1, GBK);
    asm volatile("cp.async.commit_group;" ::: "memory");

    for (int it = 0; it < KI; ++it) {
        asm volatile("cp.async.wait_group 1;" ::: "memory");
        __syncthreads();

        int ldk = it + 2;
        if (ldk < KI) load_stage(ldk % NSTAGES, ldk * GBK);
        asm volatile("cp.async.commit_group;" ::: "memory");

        uint32_t sA = smem_u32 + (it % NSTAGES) * BSTAGE_BYTES;
        uint32_t sB = sA + GBM * 128;

#pragma unroll
        for (int kst = 0; kst < 2; kst++) {
            uint32_t afh[4][4], afl[4][4];
#pragma unroll
            for (int i = 0; i < 4; i++) {
                int row = wm * 64 + i * 16 + (lane & 15);
                int ch  = kst * 2 + (lane >> 4);
                ldsm_x4(sA + row * 128 + ((ch ^ (row & 7)) * 16),
                        afh[i][0], afh[i][1], afh[i][2], afh[i][3]);
                int cl  = 4 + kst * 2 + (lane >> 4);
                ldsm_x4(sA + row * 128 + ((cl ^ (row & 7)) * 16),
                        afl[i][0], afl[i][1], afl[i][2], afl[i][3]);
            }
            uint32_t bfh[4][2], bfl[4][2];
#pragma unroll
            for (int j = 0; j < 2; j++) {
                int row = wn * 32 + j * 16 + (lane & 7) + ((lane >> 4) << 3);
                int ch  = kst * 2 + ((lane >> 3) & 1);
                uint32_t r0, r1, r2, r3;
                ldsm_x4(sB + row * 128 + ((ch ^ (row & 7)) * 16), r0, r1, r2, r3);
                bfh[2 * j][0] = r0; bfh[2 * j][1] = r1;
                bfh[2 * j + 1][0] = r2; bfh[2 * j + 1][1] = r3;
                int cl  = 4 + kst * 2 + ((lane >> 3) & 1);
                ldsm_x4(sB + row * 128 + ((cl ^ (row & 7)) * 16), r0, r1, r2, r3);
                bfl[2 * j][0] = r0; bfl[2 * j][1] = r1;
                bfl[2 * j + 1][0] = r2; bfl[2 * j + 1][1] = r3;
            }
#pragma unroll
            for (int i = 0; i < 4; i++)
#pragma unroll
                for (int j = 0; j < 4; j++) {
                    mma_bf16(acc[i][j], afh[i], bfh[j]);
                    mma_bf16(acc[i][j], afh[i], bfl[j]);
                    mma_bf16(acc[i][j], afl[i], bfh[j]);
                }
        }
    }

#pragma unroll
    for (int i = 0; i < 4; i++) {
        int m0 = bm + wm * 64 + i * 16 + (lane >> 2);
#pragma unroll
        for (int j = 0; j < 4; j++) {
            int n0 = bn + wn * 32 + j * 8 + (lane & 3) * 2;
            *(float2*)(C + (size_t)m0 * N + n0)       = make_float2(acc[i][j][0], acc[i][j][1]);
            *(float2*)(C + (size_t)(m0 + 8) * N + n0) = make_float2(acc[i][j][2], acc[i][j][3]);
        }
    }
}

// ---------------------------------------------------------------------------
// complex linear recurrence scan; emits y as bf16 hi/lo for GEMM2
// ---------------------------------------------------------------------------
__global__ __launch_bounds__(256) void scan_kernel(const float* __restrict__ a_p,
                                                   const float* __restrict__ b_p,
                                                   const float* __restrict__ c_p) {
    int warp = (blockIdx.x * blockDim.x + threadIdx.x) >> 5;
    int lane = threadIdx.x & 31;
    if (warp >= BATCH * D_MODEL) return;
    int b = warp / D_MODEL;
    int d = warp % D_MODEL;

    float ar[RANK], ai[RANK], br_[RANK], bi[RANK], cr[RANK], ci[RANK];
#pragma unroll
    for (int r = 0; r < RANK; r++) {
        int idx = (d * RANK + r) * 2;
        ar[r]  = tanhf(a_p[idx + 0]) * 0.97f;
        ai[r]  = tanhf(a_p[idx + 1]) * 0.97f;
        br_[r] = tanhf(b_p[idx + 0]);
        bi[r]  = tanhf(b_p[idx + 1]);
        cr[r]  = tanhf(c_p[idx + 0]);
        ci[r]  = tanhf(c_p[idx + 1]);
    }

    const int CH = T_LEN / 32;
    const size_t tstride = (size_t)D_MODEL * RANK * 2;
    const float* ub = g_u + (size_t)b * T_LEN * tstride + (size_t)d * RANK * 2;
    int t0 = lane * CH;

    float sr[RANK] = {0, 0, 0, 0}, si[RANK] = {0, 0, 0, 0};
    {
        const float* up = ub + (size_t)t0 * tstride;
        for (int i = 0; i < CH; i++) {
            float4 u0 = *(const float4*)(up);
            float4 u1 = *(const float4*)(up + 4);
            float ur[4] = {u0.x, u0.z, u1.x, u1.z};
            float ui[4] = {u0.y, u0.w, u1.y, u1.w};
#pragma unroll
            for (int r = 0; r < RANK; r++) {
                float nsr = ar[r] * sr[r] - ai[r] * si[r] + br_[r] * ur[r] - bi[r] * ui[r];
                float nsi = ar[r] * si[r] + ai[r] * sr[r] + br_[r] * ui[r] + bi[r] * ur[r];
                sr[r] = nsr; si[r] = nsi;
            }
            up += tstride;
        }
    }

    float Pr[RANK], Pi[RANK];
#pragma unroll
    for (int r = 0; r < RANK; r++) {
        float pr = ar[r], pi = ai[r];
#pragma unroll
        for (int s = 0; s < 6; s++) { float nr = pr * pr - pi * pi, ni = 2.f * pr * pi; pr = nr; pi = ni; }
        Pr[r] = pr; Pi[r] = pi;
    }

    for (int off = 1; off < 32; off <<= 1) {
#pragma unroll
        for (int r = 0; r < RANK; r++) {
            float prr = __shfl_up_sync(0xffffffffu, sr[r], off);
            float pri = __shfl_up_sync(0xffffffffu, si[r], off);
            if (lane >= off) {
                sr[r] += Pr[r] * prr - Pi[r] * pri;
                si[r] += Pr[r] * pri + Pi[r] * prr;
            }
        }
#pragma unroll
        for (int r = 0; r < RANK; r++) {
            float nr = Pr[r] * Pr[r] - Pi[r] * Pi[r];
            float ni = 2.f * Pr[r] * Pi[r];
            Pr[r] = nr; Pi[r] = ni;
        }
    }
#pragma unroll
    for (int r = 0; r < RANK; r++) {
        float prr = __shfl_up_sync(0xffffffffu, sr[r], 1);
        float pri = __shfl_up_sync(0xffffffffu, si[r], 1);
        sr[r] = (lane == 0) ? 0.f : prr;
        si[r] = (lane == 0) ? 0.f : pri;
    }

    {
        const float* up = ub + (size_t)t0 * tstride;
        size_t yi = (size_t)(b * T_LEN + t0) * D_MODEL + d;
        for (int i = 0; i < CH; i++) {
            float4 u0 = *(const float4*)(up);
            float4 u1 = *(const float4*)(up + 4);
            float ur[4] = {u0.x, u0.z, u1.x, u1.z};
            float ui[4] = {u0.y, u0.w, u1.y, u1.w};
            float y = 0.f;
#pragma unroll
            for (int r = 0; r < RANK; r++) {
                float nsr = ar[r] * sr[r] - ai[r] * si[r] + br_[r] * ur[r] - bi[r] * ui[r];
                float nsi = ar[r] * si[r] + ai[r] * sr[r] + br_[r] * ui[r] + bi[r] * ur[r];
                sr[r] = nsr; si[r] = nsi;
                y += cr[r] * nsr - ci[r] * nsi;
            }
            __nv_bfloat16 h, l;
            split_bf16(y, h, l);
            g_y_hi[yi] = h;
            g_y_lo[yi] = l;
            up += tstride;
            yi += D_MODEL;
        }
    }
}

// ---------------------------------------------------------------------------
extern "C" void kernel_launch(void* const* d_in, const int* in_sizes, int n_in,
                              void* d_out, int out_size) {
    const float* x      = (const float*)d_in[0];
    const float* norm_w = (const float*)d_in[1];
    const float* W_in   = (const float*)d_in[2];
    const float* W_out  = (const float*)d_in[3];
    const float* a_p    = (const float*)d_in[4];
    const float* b_p    = (const float*)d_in[5];
    const float* c_p    = (const float*)d_in[6];
    float* out = (float*)d_out;

    float* u_ptr;
    __half *xnh, *xnl, *wih;
    __nv_bfloat16 *yh, *yl, *woh, *wol;
    cudaGetSymbolAddress((void**)&u_ptr, g_u);
    cudaGetSymbolAddress((void**)&xnh, g_xn_hi);
    cudaGetSymbolAddress((void**)&xnl, g_xn_lo);
    cudaGetSymbolAddress((void**)&wih, g_wi_h);
    cudaGetSymbolAddress((void**)&yh,  g_y_hi);
    cudaGetSymbolAddress((void**)&yl,  g_y_lo);
    cudaGetSymbolAddress((void**)&woh, g_wo_hi);
    cudaGetSymbolAddress((void**)&wol, g_wo_lo);

    static bool attr_set = false;
    if (!attr_set) {
        cudaFuncSetAttribute(gemm_f16x2, cudaFuncAttributeMaxDynamicSharedMemorySize,
                             NSTAGES * F16_STAGE);
        cudaFuncSetAttribute(gemm_bf16x3, cudaFuncAttributeMaxDynamicSharedMemorySize,
                             NSTAGES * BSTAGE_BYTES);
        attr_set = true;
    }

    // weight prep
    round_kernel_f16<<<(N_IN * D_MODEL) / 1024, 256>>>(W_in, wih);
    split_kernel_bf16<<<(D_MODEL * D_MODEL) / 1024, 256>>>(W_out, woh, wol);

    // RMSNorm -> fp16 hi/lo
    rmsnorm_kernel<<<NTOK, 256>>>(x, norm_w);

    // u = xn @ W_in^T  (M=4096, N=6144, K=768) — 2-term fp16
    {
        dim3 grid(N_IN / GBN, NTOK / GBM);
        gemm_f16x2<<<grid, 256, NSTAGES * F16_STAGE>>>(xnh, xnl, wih, u_ptr,
                                                       N_IN, D_MODEL);
    }

    // scan -> y (bf16 hi/lo)
    {
        int warps = BATCH * D_MODEL;
        int blocks = (warps * 32 + 255) / 256;
        scan_kernel<<<blocks, 256>>>(a_p, b_p, c_p);
    }

    // out = y @ W_out^T (M=4096, N=768, K=768) — 3-term bf16
    {
        dim3 grid(D_MODEL / GBN, NTOK / GBM);
        gemm_bf16x3<<<grid, 256, NSTAGES * BSTAGE_BYTES>>>(yh, yl, woh, wol,
                                                           out, D_MODEL, D_MODEL);
    }
}

// round 12
// speedup vs baseline: 3.2737x; 1.1221x over previous
#include <cuda_runtime.h>
#include <cuda_bf16.h>
#include <cuda_fp16.h>
#include <cstdint>

#define D_MODEL 768
#define RANK    4
#define BATCH   2
#define T_LEN   2048
#define NTOK    (BATCH * T_LEN)        // 4096
#define N_IN    (D_MODEL * RANK * 2)   // 6144

// ---------------- scratch (device globals; allocation-free rule) ----------------
__device__ __half  g_u    [(size_t)NTOK * N_IN];      // 50.3 MB fp16
__device__ __half  g_xn_hi[(size_t)NTOK * D_MODEL];
__device__ __half  g_xn_lo[(size_t)NTOK * D_MODEL];
__device__ __half  g_y_hi [(size_t)NTOK * D_MODEL];
__device__ __half  g_y_lo [(size_t)NTOK * D_MODEL];
__device__ __half  g_wi_h [(size_t)N_IN * D_MODEL];   // W_in fp16
__device__ __half  g_wo_h [(size_t)D_MODEL * D_MODEL];// W_out fp16

// ---------------------------------------------------------------------------
// helpers
// ---------------------------------------------------------------------------
__device__ __forceinline__ void split_f16(float v, __half& h, __half& l) {
    h = __float2half_rn(v);
    l = __float2half_rn(v - __half2float(h));
}

__device__ __forceinline__ void ldsm_x4(uint32_t addr, uint32_t& r0, uint32_t& r1,
                                        uint32_t& r2, uint32_t& r3) {
    asm volatile("ldmatrix.sync.aligned.m8n8.x4.shared.b16 {%0,%1,%2,%3}, [%4];"
                 : "=r"(r0), "=r"(r1), "=r"(r2), "=r"(r3) : "r"(addr));
}

__device__ __forceinline__ void mma_f16(float* c, const uint32_t* a, const uint32_t* b) {
    asm volatile(
        "mma.sync.aligned.m16n8k16.row.col.f32.f16.f16.f32 "
        "{%0,%1,%2,%3}, {%4,%5,%6,%7}, {%8,%9}, {%0,%1,%2,%3};"
        : "+f"(c[0]), "+f"(c[1]), "+f"(c[2]), "+f"(c[3])
        : "r"(a[0]), "r"(a[1]), "r"(a[2]), "r"(a[3]), "r"(b[0]), "r"(b[1]));
}

#define CP_ASYNC16(dst, src) \
    asm volatile("cp.async.cg.shared.global [%0], [%1], 16;" :: "r"(dst), "l"(src))

// B-tile swizzle for 64B rows: 4 chunks of 16B, conflict-free over 8-row ldsm groups
#define BSWZ(row, c) (((c) ^ ((row) & 3) ^ (((row) >> 2) & 3)))

// ---------------------------------------------------------------------------
// weight rounding: fp32 -> fp16
// ---------------------------------------------------------------------------
__global__ __launch_bounds__(256) void round_kernel_f16(const float* __restrict__ src,
                                                        __half* __restrict__ dst) {
    int i = (blockIdx.x * 256 + threadIdx.x) * 4;
    float4 v = *(const float4*)(src + i);
    *(__half2*)(dst + i)     = __half2(__float2half_rn(v.x), __float2half_rn(v.y));
    *(__half2*)(dst + i + 2) = __half2(__float2half_rn(v.z), __float2half_rn(v.w));
}

// ---------------------------------------------------------------------------
// RMSNorm -> split fp16 hi/lo
// ---------------------------------------------------------------------------
__global__ __launch_bounds__(256) void rmsnorm_kernel(const float* __restrict__ x,
                                                      const float* __restrict__ w) {
    int tok = blockIdx.x;
    const float* xr = x + (size_t)tok * D_MODEL;
    int t = threadIdx.x;

    float v[3];
    float ss = 0.f;
#pragma unroll
    for (int i = 0; i < 3; i++) { v[i] = xr[t + 256 * i]; ss += v[i] * v[i]; }

    __shared__ float red[8];
#pragma unroll
    for (int off = 16; off; off >>= 1) ss += __shfl_down_sync(0xffffffffu, ss, off);
    if ((t & 31) == 0) red[t >> 5] = ss;
    __syncthreads();
    if (t < 8) {
        float s = red[t];
#pragma unroll
        for (int off = 4; off; off >>= 1) s += __shfl_down_sync(0xffu, s, off);
        if (t == 0) red[0] = s;
    }
    __syncthreads();
    float scale = rsqrtf(red[0] * (1.0f / D_MODEL) + 1e-6f);
#pragma unroll
    for (int i = 0; i < 3; i++) {
        int idx = tok * D_MODEL + t + 256 * i;
        __half h, l;
        split_f16(v[i] * scale * w[t + 256 * i], h, l);
        g_xn_hi[idx] = h;
        g_xn_lo[idx] = l;
    }
}

// ---------------------------------------------------------------------------
// fp16x2 GEMM (NT): C[m,n] = sum_k (Ahi+Alo)[m,k] * B[n,k]   (2 MMA terms)
// A hi/lo fp16, B single fp16. BM=128, BN=128, BK=32, 3-stage cp.async.
// Output templated: fp16 (for u) or fp32 (for final out).
// ---------------------------------------------------------------------------
#define GBM 128
#define GBN 128
#define GBK 32
#define F16_A_BYTES (GBM * 128)
#define F16_B_BYTES (GBN * 64)
#define F16_STAGE   (F16_A_BYTES + F16_B_BYTES)      // 24576
#define NSTAGES 3

template <typename OutT>
__global__ __launch_bounds__(256, 2) void gemm_f16x2(
    const __half* __restrict__ Ahi, const __half* __restrict__ Alo,
    const __half* __restrict__ Bh,
    OutT* __restrict__ C, int N, int K) {

    extern __shared__ char smem[];
    const uint32_t smem_u32 = (uint32_t)__cvta_generic_to_shared(smem);

    const int t    = threadIdx.x;
    const int lane = t & 31;
    const int wid  = t >> 5;
    const int wm   = wid & 1;
    const int wn   = wid >> 1;

    const int bm = blockIdx.y * GBM;
    const int bn = blockIdx.x * GBN;

    const int alc   = t & 7;          // A chunk (0-3 hi, 4-7 lo)
    const int arow0 = t >> 3;         // 0..31
    const int akoff = (alc & 3) * 8;
    const bool ahi  = alc < 4;
    const int blc   = t & 3;          // B chunk
    const int brow0 = t >> 2;         // 0..63
    const int bkoff = blc * 8;

    float acc[4][4][4];
#pragma unroll
    for (int i = 0; i < 4; i++)
#pragma unroll
        for (int j = 0; j < 4; j++)
#pragma unroll
            for (int q = 0; q < 4; q++) acc[i][j][q] = 0.f;

    const int KI = K / GBK;

    auto load_stage = [&](int stage, int k0) {
        uint32_t sA = smem_u32 + stage * F16_STAGE;
        uint32_t sB = sA + F16_A_BYTES;
#pragma unroll
        for (int p = 0; p < 4; p++) {
            int m = arow0 + p * 32;
            const __half* srcA = (ahi ? Ahi : Alo) + (size_t)(bm + m) * K + k0 + akoff;
            CP_ASYNC16(sA + m * 128 + ((alc ^ (m & 7)) * 16), srcA);
        }
#pragma unroll
        for (int p = 0; p < 2; p++) {
            int n = brow0 + p * 64;
            const __half* srcB = Bh + (size_t)(bn + n) * K + k0 + bkoff;
            CP_ASYNC16(sB + n * 64 + (BSWZ(n, blc) * 16), srcB);
        }
    };

    load_stage(0, 0);
    asm volatile("cp.async.commit_group;" ::: "memory");
    load_stage(1, GBK);
    asm volatile("cp.async.commit_group;" ::: "memory");

    for (int it = 0; it < KI; ++it) {
        asm volatile("cp.async.wait_group 1;" ::: "memory");
        __syncthreads();

        int ldk = it + 2;
        if (ldk < KI) load_stage(ldk % NSTAGES, ldk * GBK);
        asm volatile("cp.async.commit_group;" ::: "memory");

        uint32_t sA = smem_u32 + (it % NSTAGES) * F16_STAGE;
        uint32_t sB = sA + F16_A_BYTES;

#pragma unroll
        for (int kst = 0; kst < 2; kst++) {
            uint32_t afh[4][4], afl[4][4];
#pragma unroll
            for (int i = 0; i < 4; i++) {
                int row = wm * 64 + i * 16 + (lane & 15);
                int ch  = kst * 2 + (lane >> 4);
                ldsm_x4(sA + row * 128 + ((ch ^ (row & 7)) * 16),
                        afh[i][0], afh[i][1], afh[i][2], afh[i][3]);
                int cl  = 4 + kst * 2 + (lane >> 4);
                ldsm_x4(sA + row * 128 + ((cl ^ (row & 7)) * 16),
                        afl[i][0], afl[i][1], afl[i][2], afl[i][3]);
            }
            uint32_t bf[4][2];
#pragma unroll
            for (int j = 0; j < 2; j++) {
                int row = wn * 32 + j * 16 + (lane & 7) + ((lane >> 4) << 3);
                int ch  = kst * 2 + ((lane >> 3) & 1);
                uint32_t r0, r1, r2, r3;
                ldsm_x4(sB + row * 64 + (BSWZ(row, ch) * 16), r0, r1, r2, r3);
                bf[2 * j][0] = r0; bf[2 * j][1] = r1;
                bf[2 * j + 1][0] = r2; bf[2 * j + 1][1] = r3;
            }
#pragma unroll
            for (int i = 0; i < 4; i++)
#pragma unroll
                for (int j = 0; j < 4; j++) {
                    mma_f16(acc[i][j], afh[i], bf[j]);
                    mma_f16(acc[i][j], afl[i], bf[j]);
                }
        }
    }

#pragma unroll
    for (int i = 0; i < 4; i++) {
        int m0 = bm + wm * 64 + i * 16 + (lane >> 2);
#pragma unroll
        for (int j = 0; j < 4; j++) {
            int n0 = bn + wn * 32 + j * 8 + (lane & 3) * 2;
            if constexpr (sizeof(OutT) == 2) {
                *(__half2*)((__half*)C + (size_t)m0 * N + n0) =
                    __floats2half2_rn(acc[i][j][0], acc[i][j][1]);
                *(__half2*)((__half*)C + (size_t)(m0 + 8) * N + n0) =
                    __floats2half2_rn(acc[i][j][2], acc[i][j][3]);
            } else {
                *(float2*)((float*)C + (size_t)m0 * N + n0) =
                    make_float2(acc[i][j][0], acc[i][j][1]);
                *(float2*)((float*)C + (size_t)(m0 + 8) * N + n0) =
                    make_float2(acc[i][j][2], acc[i][j][3]);
            }
        }
    }
}

// ---------------------------------------------------------------------------
// complex linear recurrence scan over fp16 u; emits y as fp16 hi/lo
// ---------------------------------------------------------------------------
__global__ __launch_bounds__(256) void scan_kernel(const float* __restrict__ a_p,
                                                   const float* __restrict__ b_p,
                                                   const float* __restrict__ c_p) {
    int warp = (blockIdx.x * blockDim.x + threadIdx.x) >> 5;
    int lane = threadIdx.x & 31;
    if (warp >= BATCH * D_MODEL) return;
    int b = warp / D_MODEL;
    int d = warp % D_MODEL;

    float ar[RANK], ai[RANK], br_[RANK], bi[RANK], cr[RANK], ci[RANK];
#pragma unroll
    for (int r = 0; r < RANK; r++) {
        int idx = (d * RANK + r) * 2;
        ar[r]  = tanhf(a_p[idx + 0]) * 0.97f;
        ai[r]  = tanhf(a_p[idx + 1]) * 0.97f;
        br_[r] = tanhf(b_p[idx + 0]);
        bi[r]  = tanhf(b_p[idx + 1]);
        cr[r]  = tanhf(c_p[idx + 0]);
        ci[r]  = tanhf(c_p[idx + 1]);
    }

    const int CH = T_LEN / 32;                        // 64
    const size_t tstride = (size_t)D_MODEL * RANK * 2; // 6144 halves per t
    const __half* ub = g_u + (size_t)b * T_LEN * tstride + (size_t)d * RANK * 2;
    int t0 = lane * CH;

    float sr[RANK] = {0, 0, 0, 0}, si[RANK] = {0, 0, 0, 0};
    {
        const __half* up = ub + (size_t)t0 * tstride;
        for (int i = 0; i < CH; i++) {
            uint4 raw = *(const uint4*)(up);
            const __half2* hp = (const __half2*)&raw;
            float ur[4], ui[4];
#pragma unroll
            for (int r = 0; r < RANK; r++) {
                float2 p = __half22float2(hp[r]);
                ur[r] = p.x; ui[r] = p.y;
            }
#pragma unroll
            for (int r = 0; r < RANK; r++) {
                float nsr = ar[r] * sr[r] - ai[r] * si[r] + br_[r] * ur[r] - bi[r] * ui[r];
                float nsi = ar[r] * si[r] + ai[r] * sr[r] + br_[r] * ui[r] + bi[r] * ur[r];
                sr[r] = nsr; si[r] = nsi;
            }
            up += tstride;
        }
    }

    float Pr[RANK], Pi[RANK];
#pragma unroll
    for (int r = 0; r < RANK; r++) {
        float pr = ar[r], pi = ai[r];
#pragma unroll
        for (int s = 0; s < 6; s++) { float nr = pr * pr - pi * pi, ni = 2.f * pr * pi; pr = nr; pi = ni; }
        Pr[r] = pr; Pi[r] = pi;
    }

    for (int off = 1; off < 32; off <<= 1) {
#pragma unroll
        for (int r = 0; r < RANK; r++) {
            float prr = __shfl_up_sync(0xffffffffu, sr[r], off);
            float pri = __shfl_up_sync(0xffffffffu, si[r], off);
            if (lane >= off) {
                sr[r] += Pr[r] * prr - Pi[r] * pri;
                si[r] += Pr[r] * pri + Pi[r] * prr;
            }
        }
#pragma unroll
        for (int r = 0; r < RANK; r++) {
            float nr = Pr[r] * Pr[r] - Pi[r] * Pi[r];
            float ni = 2.f * Pr[r] * Pi[r];
            Pr[r] = nr; Pi[r] = ni;
        }
    }
#pragma unroll
    for (int r = 0; r < RANK; r++) {
        float prr = __shfl_up_sync(0xffffffffu, sr[r], 1);
        float pri = __shfl_up_sync(0xffffffffu, si[r], 1);
        sr[r] = (lane == 0) ? 0.f : prr;
        si[r] = (lane == 0) ? 0.f : pri;
    }

    {
        const __half* up = ub + (size_t)t0 * tstride;
        size_t yi = (size_t)(b * T_LEN + t0) * D_MODEL + d;
        for (int i = 0; i < CH; i++) {
            uint4 raw = *(const uint4*)(up);
            const __half2* hp = (const __half2*)&raw;
            float ur[4], ui[4];
#pragma unroll
            for (int r = 0; r < RANK; r++) {
                float2 p = __half22float2(hp[r]);
                ur[r] = p.x; ui[r] = p.y;
            }
            float y = 0.f;
#pragma unroll
            for (int r = 0; r < RANK; r++) {
                float nsr = ar[r] * sr[r] - ai[r] * si[r] + br_[r] * ur[r] - bi[r] * ui[r];
                float nsi = ar[r] * si[r] + ai[r] * sr[r] + br_[r] * ui[r] + bi[r] * ur[r];
                sr[r] = nsr; si[r] = nsi;
                y += cr[r] * nsr - ci[r] * nsi;
            }
            __half h, l;
            split_f16(y, h, l);
            g_y_hi[yi] = h;
            g_y_lo[yi] = l;
            up += tstride;
            yi += D_MODEL;
        }
    }
}

// ---------------------------------------------------------------------------
extern "C" void kernel_launch(void* const* d_in, const int* in_sizes, int n_in,
                              void* d_out, int out_size) {
    const float* x      = (const float*)d_in[0];
    const float* norm_w = (const float*)d_in[1];
    const float* W_in   = (const float*)d_in[2];
    const float* W_out  = (const float*)d_in[3];
    const float* a_p    = (const float*)d_in[4];
    const float* b_p    = (const float*)d_in[5];
    const float* c_p    = (const float*)d_in[6];
    float* out = (float*)d_out;

    __half *u_ptr, *xnh, *xnl, *wih, *yh, *yl, *woh;
    cudaGetSymbolAddress((void**)&u_ptr, g_u);
    cudaGetSymbolAddress((void**)&xnh, g_xn_hi);
    cudaGetSymbolAddress((void**)&xnl, g_xn_lo);
    cudaGetSymbolAddress((void**)&wih, g_wi_h);
    cudaGetSymbolAddress((void**)&yh,  g_y_hi);
    cudaGetSymbolAddress((void**)&yl,  g_y_lo);
    cudaGetSymbolAddress((void**)&woh, g_wo_h);

    static bool attr_set = false;
    if (!attr_set) {
        cudaFuncSetAttribute(gemm_f16x2<__half>, cudaFuncAttributeMaxDynamicSharedMemorySize,
                             NSTAGES * F16_STAGE);
        cudaFuncSetAttribute(gemm_f16x2<float>, cudaFuncAttributeMaxDynamicSharedMemorySize,
                             NSTAGES * F16_STAGE);
        attr_set = true;
    }

    // weight prep
    round_kernel_f16<<<(N_IN * D_MODEL) / 1024, 256>>>(W_in, wih);
    round_kernel_f16<<<(D_MODEL * D_MODEL) / 1024, 256>>>(W_out, woh);

    // RMSNorm -> fp16 hi/lo
    rmsnorm_kernel<<<NTOK, 256>>>(x, norm_w);

    // u = xn @ W_in^T  (M=4096, N=6144, K=768) -> fp16
    {
        dim3 grid(N_IN / GBN, NTOK / GBM);
        gemm_f16x2<__half><<<grid, 256, NSTAGES * F16_STAGE>>>(xnh, xnl, wih, u_ptr,
                                                               N_IN, D_MODEL);
    }

    // scan -> y (fp16 hi/lo)
    {
        int warps = BATCH * D_MODEL;
        int blocks = (warps * 32 + 255) / 256;
        scan_kernel<<<blocks, 256>>>(a_p, b_p, c_p);
    }

    // out = y @ W_out^T (M=4096, N=768, K=768) -> fp32
    {
        dim3 grid(D_MODEL / GBN, NTOK / GBM);
        gemm_f16x2<float><<<grid, 256, NSTAGES * F16_STAGE>>>(yh, yl, woh, out,
                                                              D_MODEL, D_MODEL);
    }
}

// round 14
// speedup vs baseline: 4.2521x; 1.2989x over previous
#include <cuda_runtime.h>
#include <cuda_bf16.h>
#include <cuda_fp16.h>
#include <cstdint>

#define D_MODEL 768
#define RANK    4
#define BATCH   2
#define T_LEN   2048
#define NTOK    (BATCH * T_LEN)        // 4096
#define N_IN    (D_MODEL * RANK * 2)   // 6144
#define NC      64                     // scan chunks over time
#define TL      (T_LEN / NC)           // 32 timesteps per chunk

// ---------------- scratch (device globals; allocation-free rule) ----------------
__device__ __half  g_u    [(size_t)NTOK * N_IN];      // 50.3 MB fp16
__device__ __half  g_xn_hi[(size_t)NTOK * D_MODEL];
__device__ __half  g_xn_lo[(size_t)NTOK * D_MODEL];
__device__ __half  g_y_hi [(size_t)NTOK * D_MODEL];
__device__ __half  g_y_lo [(size_t)NTOK * D_MODEL];
__device__ __half  g_wi_h [(size_t)N_IN * D_MODEL];   // W_in fp16
__device__ __half  g_wo_h [(size_t)D_MODEL * D_MODEL];// W_out fp16
// per-chunk partial states / carry-ins: [c][b][d][r] float2 (3.1 MB)
__device__ float2  g_ps   [(size_t)NC * BATCH * D_MODEL * RANK];

// ---------------------------------------------------------------------------
// helpers
// ---------------------------------------------------------------------------
__device__ __forceinline__ void split_f16(float v, __half& h, __half& l) {
    h = __float2half_rn(v);
    l = __float2half_rn(v - __half2float(h));
}

__device__ __forceinline__ void ldsm_x4(uint32_t addr, uint32_t& r0, uint32_t& r1,
                                        uint32_t& r2, uint32_t& r3) {
    asm volatile("ldmatrix.sync.aligned.m8n8.x4.shared.b16 {%0,%1,%2,%3}, [%4];"
                 : "=r"(r0), "=r"(r1), "=r"(r2), "=r"(r3) : "r"(addr));
}

__device__ __forceinline__ void mma_f16(float* c, const uint32_t* a, const uint32_t* b) {
    asm volatile(
        "mma.sync.aligned.m16n8k16.row.col.f32.f16.f16.f32 "
        "{%0,%1,%2,%3}, {%4,%5,%6,%7}, {%8,%9}, {%0,%1,%2,%3};"
        : "+f"(c[0]), "+f"(c[1]), "+f"(c[2]), "+f"(c[3])
        : "r"(a[0]), "r"(a[1]), "r"(a[2]), "r"(a[3]), "r"(b[0]), "r"(b[1]));
}

#define CP_ASYNC16(dst, src) \
    asm volatile("cp.async.cg.shared.global [%0], [%1], 16;" :: "r"(dst), "l"(src))

#define BSWZ(row, c) (((c) ^ ((row) & 3) ^ (((row) >> 2) & 3)))

// ---------------------------------------------------------------------------
// weight rounding: fp32 -> fp16
// ---------------------------------------------------------------------------
__global__ __launch_bounds__(256) void round_kernel_f16(const float* __restrict__ src,
                                                        __half* __restrict__ dst) {
    int i = (blockIdx.x * 256 + threadIdx.x) * 4;
    float4 v = *(const float4*)(src + i);
    *(__half2*)(dst + i)     = __half2(__float2half_rn(v.x), __float2half_rn(v.y));
    *(__half2*)(dst + i + 2) = __half2(__float2half_rn(v.z), __float2half_rn(v.w));
}

// ---------------------------------------------------------------------------
// RMSNorm -> split fp16 hi/lo
// ---------------------------------------------------------------------------
__global__ __launch_bounds__(256) void rmsnorm_kernel(const float* __restrict__ x,
                                                      const float* __restrict__ w) {
    int tok = blockIdx.x;
    const float* xr = x + (size_t)tok * D_MODEL;
    int t = threadIdx.x;

    float v[3];
    float ss = 0.f;
#pragma unroll
    for (int i = 0; i < 3; i++) { v[i] = xr[t + 256 * i]; ss += v[i] * v[i]; }

    __shared__ float red[8];
#pragma unroll
    for (int off = 16; off; off >>= 1) ss += __shfl_down_sync(0xffffffffu, ss, off);
    if ((t & 31) == 0) red[t >> 5] = ss;
    __syncthreads();
    if (t < 8) {
        float s = red[t];
#pragma unroll
        for (int off = 4; off; off >>= 1) s += __shfl_down_sync(0xffu, s, off);
        if (t == 0) red[0] = s;
    }
    __syncthreads();
    float scale = rsqrtf(red[0] * (1.0f / D_MODEL) + 1e-6f);
#pragma unroll
    for (int i = 0; i < 3; i++) {
        int idx = tok * D_MODEL + t + 256 * i;
        __half h, l;
        split_f16(v[i] * scale * w[t + 256 * i], h, l);
        g_xn_hi[idx] = h;
        g_xn_lo[idx] = l;
    }
}

// ---------------------------------------------------------------------------
// fp16x2 GEMM (NT): C[m,n] = sum_k (Ahi+Alo)[m,k] * B[n,k]   (2 MMA terms)
// ---------------------------------------------------------------------------
#define GBM 128
#define GBN 128
#define GBK 32
#define F16_A_BYTES (GBM * 128)
#define F16_B_BYTES (GBN * 64)
#define F16_STAGE   (F16_A_BYTES + F16_B_BYTES)
#define NSTAGES 3

template <typename OutT>
__global__ __launch_bounds__(256, 2) void gemm_f16x2(
    const __half* __restrict__ Ahi, const __half* __restrict__ Alo,
    const __half* __restrict__ Bh,
    OutT* __restrict__ C, int N, int K) {

    extern __shared__ char smem[];
    const uint32_t smem_u32 = (uint32_t)__cvta_generic_to_shared(smem);

    const int t    = threadIdx.x;
    const int lane = t & 31;
    const int wid  = t >> 5;
    const int wm   = wid & 1;
    const int wn   = wid >> 1;

    const int bm = blockIdx.y * GBM;
    const int bn = blockIdx.x * GBN;

    const int alc   = t & 7;
    const int arow0 = t >> 3;
    const int akoff = (alc & 3) * 8;
    const bool ahi  = alc < 4;
    const int blc   = t & 3;
    const int brow0 = t >> 2;
    const int bkoff = blc * 8;

    float acc[4][4][4];
#pragma unroll
    for (int i = 0; i < 4; i++)
#pragma unroll
        for (int j = 0; j < 4; j++)
#pragma unroll
            for (int q = 0; q < 4; q++) acc[i][j][q] = 0.f;

    const int KI = K / GBK;

    auto load_stage = [&](int stage, int k0) {
        uint32_t sA = smem_u32 + stage * F16_STAGE;
        uint32_t sB = sA + F16_A_BYTES;
#pragma unroll
        for (int p = 0; p < 4; p++) {
            int m = arow0 + p * 32;
            const __half* srcA = (ahi ? Ahi : Alo) + (size_t)(bm + m) * K + k0 + akoff;
            CP_ASYNC16(sA + m * 128 + ((alc ^ (m & 7)) * 16), srcA);
        }
#pragma unroll
        for (int p = 0; p < 2; p++) {
            int n = brow0 + p * 64;
            const __half* srcB = Bh + (size_t)(bn + n) * K + k0 + bkoff;
            CP_ASYNC16(sB + n * 64 + (BSWZ(n, blc) * 16), srcB);
        }
    };

    load_stage(0, 0);
    asm volatile("cp.async.commit_group;" ::: "memory");
    load_stage(1, GBK);
    asm volatile("cp.async.commit_group;" ::: "memory");

    for (int it = 0; it < KI; ++it) {
        asm volatile("cp.async.wait_group 1;" ::: "memory");
        __syncthreads();

        int ldk = it + 2;
        if (ldk < KI) load_stage(ldk % NSTAGES, ldk * GBK);
        asm volatile("cp.async.commit_group;" ::: "memory");

        uint32_t sA = smem_u32 + (it % NSTAGES) * F16_STAGE;
        uint32_t sB = sA + F16_A_BYTES;

#pragma unroll
        for (int kst = 0; kst < 2; kst++) {
            uint32_t afh[4][4], afl[4][4];
#pragma unroll
            for (int i = 0; i < 4; i++) {
                int row = wm * 64 + i * 16 + (lane & 15);
                int ch  = kst * 2 + (lane >> 4);
                ldsm_x4(sA + row * 128 + ((ch ^ (row & 7)) * 16),
                        afh[i][0], afh[i][1], afh[i][2], afh[i][3]);
                int cl  = 4 + kst * 2 + (lane >> 4);
                ldsm_x4(sA + row * 128 + ((cl ^ (row & 7)) * 16),
                        afl[i][0], afl[i][1], afl[i][2], afl[i][3]);
            }
            uint32_t bf[4][2];
#pragma unroll
            for (int j = 0; j < 2; j++) {
                int row = wn * 32 + j * 16 + (lane & 7) + ((lane >> 4) << 3);
                int ch  = kst * 2 + ((lane >> 3) & 1);
                uint32_t r0, r1, r2, r3;
                ldsm_x4(sB + row * 64 + (BSWZ(row, ch) * 16), r0, r1, r2, r3);
                bf[2 * j][0] = r0; bf[2 * j][1] = r1;
                bf[2 * j + 1][0] = r2; bf[2 * j + 1][1] = r3;
            }
#pragma unroll
            for (int i = 0; i < 4; i++)
#pragma unroll
                for (int j = 0; j < 4; j++) {
                    mma_f16(acc[i][j], afh[i], bf[j]);
                    mma_f16(acc[i][j], afl[i], bf[j]);
                }
        }
    }

#pragma unroll
    for (int i = 0; i < 4; i++) {
        int m0 = bm + wm * 64 + i * 16 + (lane >> 2);
#pragma unroll
        for (int j = 0; j < 4; j++) {
            int n0 = bn + wn * 32 + j * 8 + (lane & 3) * 2;
            if constexpr (sizeof(OutT) == 2) {
                *(__half2*)((__half*)C + (size_t)m0 * N + n0) =
                    __floats2half2_rn(acc[i][j][0], acc[i][j][1]);
                *(__half2*)((__half*)C + (size_t)(m0 + 8) * N + n0) =
                    __floats2half2_rn(acc[i][j][2], acc[i][j][3]);
            } else {
                *(float2*)((float*)C + (size_t)m0 * N + n0) =
                    make_float2(acc[i][j][0], acc[i][j][1]);
                *(float2*)((float*)C + (size_t)(m0 + 8) * N + n0) =
                    make_float2(acc[i][j][2], acc[i][j][3]);
            }
        }
    }
}

// ---------------------------------------------------------------------------
// SCAN, coalesced layout. Thread = one d-channel (4 complex ranks, 16B/t).
// Grid: (NC chunks, 3 d-slices of 256, BATCH). Warp lanes = consecutive d
// -> per-t warp load = 512B contiguous; y store = 64B contiguous.
// ---------------------------------------------------------------------------
// pass 1: per-chunk contribution with zero init -> g_ps[c][b][d][r]
__global__ __launch_bounds__(256) void scan_pass1(const float* __restrict__ a_p,
                                                  const float* __restrict__ b_p) {
    const int c   = blockIdx.x;
    const int sl  = blockIdx.y;
    const int b   = blockIdx.z;
    const int d   = sl * 256 + threadIdx.x;

    float ar[RANK], ai[RANK], br_[RANK], bi[RANK];
#pragma unroll
    for (int r = 0; r < RANK; r++) {
        int idx = (d * RANK + r) * 2;
        ar[r]  = tanhf(a_p[idx + 0]) * 0.97f;
        ai[r]  = tanhf(a_p[idx + 1]) * 0.97f;
        br_[r] = tanhf(b_p[idx + 0]);
        bi[r]  = tanhf(b_p[idx + 1]);
    }

    const __half* up = g_u + ((size_t)(b * T_LEN + c * TL)) * N_IN + (size_t)d * 8;

    float sr[RANK] = {0, 0, 0, 0}, si[RANK] = {0, 0, 0, 0};
#pragma unroll 4
    for (int i = 0; i < TL; i++) {
        uint4 raw = *(const uint4*)(up);
        const __half2* hp = (const __half2*)&raw;
#pragma unroll
        for (int r = 0; r < RANK; r++) {
            float2 p = __half22float2(hp[r]);
            float nsr = ar[r] * sr[r] - ai[r] * si[r] + br_[r] * p.x - bi[r] * p.y;
            float nsi = ar[r] * si[r] + ai[r] * sr[r] + br_[r] * p.y + bi[r] * p.x;
            sr[r] = nsr; si[r] = nsi;
        }
        up += N_IN;
    }

    float2* ps = g_ps + ((size_t)(c * BATCH + b) * D_MODEL + d) * RANK;
#pragma unroll
    for (int r = 0; r < RANK; r++) ps[r] = make_float2(sr[r], si[r]);
}

// carry: serial prefix over NC chunks per (b,d,r); in-place S -> carry-in
__global__ __launch_bounds__(256) void scan_carry(const float* __restrict__ a_p) {
    int g = blockIdx.x * 256 + threadIdx.x;           // 0..6143
    int b = g / (D_MODEL * RANK);
    int rem = g % (D_MODEL * RANK);                   // d*4 + r
    // coefficient a for this (d,r)
    float arr = tanhf(a_p[rem * 2 + 0]) * 0.97f;
    float aii = tanhf(a_p[rem * 2 + 1]) * 0.97f;
    // A = a^TL (TL=32 -> 5 squarings)
#pragma unroll
    for (int s = 0; s < 5; s++) {
        float nr = arr * arr - aii * aii;
        float ni = 2.f * arr * aii;
        arr = nr; aii = ni;
    }
    float rr = 0.f, ri = 0.f;
    for (int c = 0; c < NC; c++) {
        size_t idx = (size_t)(c * BATCH + b) * (D_MODEL * RANK) + rem;
        float2 S = g_ps[idx];
        g_ps[idx] = make_float2(rr, ri);              // exclusive carry-in
        float nrr = arr * rr - aii * ri + S.x;
        float nri = arr * ri + aii * rr + S.y;
        rr = nrr; ri = nri;
    }
}

// pass 2: replay with carry-in, emit y (fp16 hi/lo, coalesced 64B warp stores)
__global__ __launch_bounds__(256) void scan_pass2(const float* __restrict__ a_p,
                                                  const float* __restrict__ b_p,
                                                  const float* __restrict__ c_p) {
    const int c   = blockIdx.x;
    const int sl  = blockIdx.y;
    const int b   = blockIdx.z;
    const int d   = sl * 256 + threadIdx.x;

    float ar[RANK], ai[RANK], br_[RANK], bi[RANK], cr[RANK], ci[RANK];
#pragma unroll
    for (int r = 0; r < RANK; r++) {
        int idx = (d * RANK + r) * 2;
        ar[r]  = tanhf(a_p[idx + 0]) * 0.97f;
        ai[r]  = tanhf(a_p[idx + 1]) * 0.97f;
        br_[r] = tanhf(b_p[idx + 0]);
        bi[r]  = tanhf(b_p[idx + 1]);
        cr[r]  = tanhf(c_p[idx + 0]);
        ci[r]  = tanhf(c_p[idx + 1]);
    }

    float sr[RANK], si[RANK];
    const float2* ps = g_ps + ((size_t)(c * BATCH + b) * D_MODEL + d) * RANK;
#pragma unroll
    for (int r = 0; r < RANK; r++) { float2 v = ps[r]; sr[r] = v.x; si[r] = v.y; }

    const __half* up = g_u + ((size_t)(b * T_LEN + c * TL)) * N_IN + (size_t)d * 8;
    __half* yh = g_y_hi + (size_t)(b * T_LEN + c * TL) * D_MODEL + d;
    __half* yl = g_y_lo + (size_t)(b * T_LEN + c * TL) * D_MODEL + d;

#pragma unroll 4
    for (int i = 0; i < TL; i++) {
        uint4 raw = *(const uint4*)(up);
        const __half2* hp = (const __half2*)&raw;
        float y = 0.f;
#pragma unroll
        for (int r = 0; r < RANK; r++) {
            float2 p = __half22float2(hp[r]);
            float nsr = ar[r] * sr[r] - ai[r] * si[r] + br_[r] * p.x - bi[r] * p.y;
            float nsi = ar[r] * si[r] + ai[r] * sr[r] + br_[r] * p.y + bi[r] * p.x;
            sr[r] = nsr; si[r] = nsi;
            y += cr[r] * nsr - ci[r] * nsi;
        }
        __half h, l;
        split_f16(y, h, l);
        *yh = h;
        *yl = l;
        up += N_IN;
        yh += D_MODEL;
        yl += D_MODEL;
    }
}

// ---------------------------------------------------------------------------
extern "C" void kernel_launch(void* const* d_in, const int* in_sizes, int n_in,
                              void* d_out, int out_size) {
    const float* x      = (const float*)d_in[0];
    const float* norm_w = (const float*)d_in[1];
    const float* W_in   = (const float*)d_in[2];
    const float* W_out  = (const float*)d_in[3];
    const float* a_p    = (const float*)d_in[4];
    const float* b_p    = (const float*)d_in[5];
    const float* c_p    = (const float*)d_in[6];
    float* out = (float*)d_out;

    __half *u_ptr, *xnh, *xnl, *wih, *yh, *yl, *woh;
    cudaGetSymbolAddress((void**)&u_ptr, g_u);
    cudaGetSymbolAddress((void**)&xnh, g_xn_hi);
    cudaGetSymbolAddress((void**)&xnl, g_xn_lo);
    cudaGetSymbolAddress((void**)&wih, g_wi_h);
    cudaGetSymbolAddress((void**)&yh,  g_y_hi);
    cudaGetSymbolAddress((void**)&yl,  g_y_lo);
    cudaGetSymbolAddress((void**)&woh, g_wo_h);

    static bool attr_set = false;
    if (!attr_set) {
        cudaFuncSetAttribute(gemm_f16x2<__half>, cudaFuncAttributeMaxDynamicSharedMemorySize,
                             NSTAGES * F16_STAGE);
        cudaFuncSetAttribute(gemm_f16x2<float>, cudaFuncAttributeMaxDynamicSharedMemorySize,
                             NSTAGES * F16_STAGE);
        attr_set = true;
    }

    // weight prep
    round_kernel_f16<<<(N_IN * D_MODEL) / 1024, 256>>>(W_in, wih);
    round_kernel_f16<<<(D_MODEL * D_MODEL) / 1024, 256>>>(W_out, woh);

    // RMSNorm -> fp16 hi/lo
    rmsnorm_kernel<<<NTOK, 256>>>(x, norm_w);

    // u = xn @ W_in^T  (M=4096, N=6144, K=768) -> fp16
    {
        dim3 grid(N_IN / GBN, NTOK / GBM);
        gemm_f16x2<__half><<<grid, 256, NSTAGES * F16_STAGE>>>(xnh, xnl, wih, u_ptr,
                                                               N_IN, D_MODEL);
    }

    // scan: coalesced 3-kernel chunked scan -> y (fp16 hi/lo)
    {
        dim3 grid(NC, 3, BATCH);
        scan_pass1<<<grid, 256>>>(a_p, b_p);
        scan_carry<<<(BATCH * D_MODEL * RANK) / 256, 256>>>(a_p);
        scan_pass2<<<grid, 256>>>(a_p, b_p, c_p);
    }

    // out = y @ W_out^T (M=4096, N=768, K=768) -> fp32
    {
        dim3 grid(D_MODEL / GBN, NTOK / GBM);
        gemm_f16x2<float><<<grid, 256, NSTAGES * F16_STAGE>>>(yh, yl, woh, out,
                                                              D_MODEL, D_MODEL);
    }
}

// round 15
// speedup vs baseline: 6.3736x; 1.4989x over previous
#include <cuda_runtime.h>
#include <cuda_bf16.h>
#include <cuda_fp16.h>
#include <cstdint>

#define D_MODEL 768
#define RANK    4
#define BATCH   2
#define T_LEN   2048
#define NTOK    (BATCH * T_LEN)        // 4096
#define N_IN    (D_MODEL * RANK * 2)   // 6144
#define NC      64                     // scan chunks over time
#define TL      (T_LEN / NC)           // 32 timesteps per chunk

// ---------------- scratch (device globals; allocation-free rule) ----------------
__device__ __half  g_u   [(size_t)NTOK * N_IN];      // 50.3 MB fp16
__device__ __half  g_xn  [(size_t)NTOK * D_MODEL];
__device__ __half  g_y   [(size_t)NTOK * D_MODEL];
__device__ __half  g_wi_h[(size_t)N_IN * D_MODEL];   // W_in fp16
__device__ __half  g_wo_h[(size_t)D_MODEL * D_MODEL];// W_out fp16
// per-chunk partial states / carry-ins: [c][b][d][r] float2 (3.1 MB)
__device__ float2  g_ps  [(size_t)NC * BATCH * D_MODEL * RANK];

// ---------------------------------------------------------------------------
// helpers
// ---------------------------------------------------------------------------
__device__ __forceinline__ void ldsm_x4(uint32_t addr, uint32_t& r0, uint32_t& r1,
                                        uint32_t& r2, uint32_t& r3) {
    asm volatile("ldmatrix.sync.aligned.m8n8.x4.shared.b16 {%0,%1,%2,%3}, [%4];"
                 : "=r"(r0), "=r"(r1), "=r"(r2), "=r"(r3) : "r"(addr));
}

__device__ __forceinline__ void mma_f16(float* c, const uint32_t* a, const uint32_t* b) {
    asm volatile(
        "mma.sync.aligned.m16n8k16.row.col.f32.f16.f16.f32 "
        "{%0,%1,%2,%3}, {%4,%5,%6,%7}, {%8,%9}, {%0,%1,%2,%3};"
        : "+f"(c[0]), "+f"(c[1]), "+f"(c[2]), "+f"(c[3])
        : "r"(a[0]), "r"(a[1]), "r"(a[2]), "r"(a[3]), "r"(b[0]), "r"(b[1]));
}

#define CP_ASYNC16(dst, src) \
    asm volatile("cp.async.cg.shared.global [%0], [%1], 16;" :: "r"(dst), "l"(src))

// swizzle for 64B rows: 4 chunks of 16B, conflict-free over 8-row ldsm groups
#define BSWZ(row, c) (((c) ^ ((row) & 3) ^ (((row) >> 2) & 3)))

// ---------------------------------------------------------------------------
// weight rounding: fp32 -> fp16
// ---------------------------------------------------------------------------
__global__ __launch_bounds__(256) void round_kernel_f16(const float* __restrict__ src,
                                                        __half* __restrict__ dst) {
    int i = (blockIdx.x * 256 + threadIdx.x) * 4;
    float4 v = *(const float4*)(src + i);
    *(__half2*)(dst + i)     = __half2(__float2half_rn(v.x), __float2half_rn(v.y));
    *(__half2*)(dst + i + 2) = __half2(__float2half_rn(v.z), __float2half_rn(v.w));
}

// ---------------------------------------------------------------------------
// RMSNorm -> fp16
// ---------------------------------------------------------------------------
__global__ __launch_bounds__(256) void rmsnorm_kernel(const float* __restrict__ x,
                                                      const float* __restrict__ w) {
    int tok = blockIdx.x;
    const float* xr = x + (size_t)tok * D_MODEL;
    int t = threadIdx.x;

    float v[3];
    float ss = 0.f;
#pragma unroll
    for (int i = 0; i < 3; i++) { v[i] = xr[t + 256 * i]; ss += v[i] * v[i]; }

    __shared__ float red[8];
#pragma unroll
    for (int off = 16; off; off >>= 1) ss += __shfl_down_sync(0xffffffffu, ss, off);
    if ((t & 31) == 0) red[t >> 5] = ss;
    __syncthreads();
    if (t < 8) {
        float s = red[t];
#pragma unroll
        for (int off = 4; off; off >>= 1) s += __shfl_down_sync(0xffu, s, off);
        if (t == 0) red[0] = s;
    }
    __syncthreads();
    float scale = rsqrtf(red[0] * (1.0f / D_MODEL) + 1e-6f);
#pragma unroll
    for (int i = 0; i < 3; i++) {
        int idx = tok * D_MODEL + t + 256 * i;
        g_xn[idx] = __float2half_rn(v[i] * scale * w[t + 256 * i]);
    }
}

// ---------------------------------------------------------------------------
// single-term fp16 GEMM (NT): C[m,n] = sum_k A[m,k] * B[n,k], fp32 accum
// BM=128, BN=128, BK=32, 3-stage cp.async, 256 threads, warps 2(M)x4(N).
// Both A and B smem tiles: 64B rows (one BK=32 fp16 row), BSWZ swizzle.
// ---------------------------------------------------------------------------
#define GBM 128
#define GBN 128
#define GBK 32
#define F16_A_BYTES (GBM * 64)
#define F16_B_BYTES (GBN * 64)
#define F16_STAGE   (F16_A_BYTES + F16_B_BYTES)      // 16384
#define NSTAGES 3

template <typename OutT>
__global__ __launch_bounds__(256, 2) void gemm_f16(
    const __half* __restrict__ A, const __half* __restrict__ B,
    OutT* __restrict__ C, int N, int K) {

    extern __shared__ char smem[];
    const uint32_t smem_u32 = (uint32_t)__cvta_generic_to_shared(smem);

    const int t    = threadIdx.x;
    const int lane = t & 31;
    const int wid  = t >> 5;
    const int wm   = wid & 1;
    const int wn   = wid >> 1;

    const int bm = blockIdx.y * GBM;
    const int bn = blockIdx.x * GBN;

    const int lc   = t & 3;           // 16B chunk within 64B row
    const int row0 = t >> 2;          // 0..63
    const int koff = lc * 8;

    float acc[4][4][4];
#pragma unroll
    for (int i = 0; i < 4; i++)
#pragma unroll
        for (int j = 0; j < 4; j++)
#pragma unroll
            for (int q = 0; q < 4; q++) acc[i][j][q] = 0.f;

    const int KI = K / GBK;

    auto load_stage = [&](int stage, int k0) {
        uint32_t sA = smem_u32 + stage * F16_STAGE;
        uint32_t sB = sA + F16_A_BYTES;
#pragma unroll
        for (int p = 0; p < 2; p++) {
            int m = row0 + p * 64;
            const __half* srcA = A + (size_t)(bm + m) * K + k0 + koff;
            CP_ASYNC16(sA + m * 64 + (BSWZ(m, lc) * 16), srcA);
        }
#pragma unroll
        for (int p = 0; p < 2; p++) {
            int n = row0 + p * 64;
            const __half* srcB = B + (size_t)(bn + n) * K + k0 + koff;
            CP_ASYNC16(sB + n * 64 + (BSWZ(n, lc) * 16), srcB);
        }
    };

    load_stage(0, 0);
    asm volatile("cp.async.commit_group;" ::: "memory");
    load_stage(1, GBK);
    asm volatile("cp.async.commit_group;" ::: "memory");

    for (int it = 0; it < KI; ++it) {
        asm volatile("cp.async.wait_group 1;" ::: "memory");
        __syncthreads();

        int ldk = it + 2;
        if (ldk < KI) load_stage(ldk % NSTAGES, ldk * GBK);
        asm volatile("cp.async.commit_group;" ::: "memory");

        uint32_t sA = smem_u32 + (it % NSTAGES) * F16_STAGE;
        uint32_t sB = sA + F16_A_BYTES;

#pragma unroll
        for (int kst = 0; kst < 2; kst++) {
            uint32_t af[4][4];
#pragma unroll
            for (int i = 0; i < 4; i++) {
                int row = wm * 64 + i * 16 + (lane & 15);
                int ch  = kst * 2 + (lane >> 4);
                ldsm_x4(sA + row * 64 + (BSWZ(row, ch) * 16),
                        af[i][0], af[i][1], af[i][2], af[i][3]);
            }
            uint32_t bf[4][2];
#pragma unroll
            for (int j = 0; j < 2; j++) {
                int row = wn * 32 + j * 16 + (lane & 7) + ((lane >> 4) << 3);
                int ch  = kst * 2 + ((lane >> 3) & 1);
                uint32_t r0, r1, r2, r3;
                ldsm_x4(sB + row * 64 + (BSWZ(row, ch) * 16), r0, r1, r2, r3);
                bf[2 * j][0] = r0; bf[2 * j][1] = r1;
                bf[2 * j + 1][0] = r2; bf[2 * j + 1][1] = r3;
            }
#pragma unroll
            for (int i = 0; i < 4; i++)
#pragma unroll
                for (int j = 0; j < 4; j++)
                    mma_f16(acc[i][j], af[i], bf[j]);
        }
    }

#pragma unroll
    for (int i = 0; i < 4; i++) {
        int m0 = bm + wm * 64 + i * 16 + (lane >> 2);
#pragma unroll
        for (int j = 0; j < 4; j++) {
            int n0 = bn + wn * 32 + j * 8 + (lane & 3) * 2;
            if constexpr (sizeof(OutT) == 2) {
                *(__half2*)((__half*)C + (size_t)m0 * N + n0) =
                    __floats2half2_rn(acc[i][j][0], acc[i][j][1]);
                *(__half2*)((__half*)C + (size_t)(m0 + 8) * N + n0) =
                    __floats2half2_rn(acc[i][j][2], acc[i][j][3]);
            } else {
                *(float2*)((float*)C + (size_t)m0 * N + n0) =
                    make_float2(acc[i][j][0], acc[i][j][1]);
                *(float2*)((float*)C + (size_t)(m0 + 8) * N + n0) =
                    make_float2(acc[i][j][2], acc[i][j][3]);
            }
        }
    }
}

// ---------------------------------------------------------------------------
// SCAN, coalesced layout. Thread = one d-channel (4 complex ranks, 16B/t).
// ---------------------------------------------------------------------------
__global__ __launch_bounds__(256) void scan_pass1(const float* __restrict__ a_p,
                                                  const float* __restrict__ b_p) {
    const int c   = blockIdx.x;
    const int sl  = blockIdx.y;
    const int b   = blockIdx.z;
    const int d   = sl * 256 + threadIdx.x;

    float ar[RANK], ai[RANK], br_[RANK], bi[RANK];
#pragma unroll
    for (int r = 0; r < RANK; r++) {
        int idx = (d * RANK + r) * 2;
        ar[r]  = tanhf(a_p[idx + 0]) * 0.97f;
        ai[r]  = tanhf(a_p[idx + 1]) * 0.97f;
        br_[r] = tanhf(b_p[idx + 0]);
        bi[r]  = tanhf(b_p[idx + 1]);
    }

    const __half* up = g_u + ((size_t)(b * T_LEN + c * TL)) * N_IN + (size_t)d * 8;

    float sr[RANK] = {0, 0, 0, 0}, si[RANK] = {0, 0, 0, 0};
#pragma unroll 4
    for (int i = 0; i < TL; i++) {
        uint4 raw = *(const uint4*)(up);
        const __half2* hp = (const __half2*)&raw;
#pragma unroll
        for (int r = 0; r < RANK; r++) {
            float2 p = __half22float2(hp[r]);
            float nsr = ar[r] * sr[r] - ai[r] * si[r] + br_[r] * p.x - bi[r] * p.y;
            float nsi = ar[r] * si[r] + ai[r] * sr[r] + br_[r] * p.y + bi[r] * p.x;
            sr[r] = nsr; si[r] = nsi;
        }
        up += N_IN;
    }

    float2* ps = g_ps + ((size_t)(c * BATCH + b) * D_MODEL + d) * RANK;
#pragma unroll
    for (int r = 0; r < RANK; r++) ps[r] = make_float2(sr[r], si[r]);
}

__global__ __launch_bounds__(256) void scan_carry(const float* __restrict__ a_p) {
    int g = blockIdx.x * 256 + threadIdx.x;           // 0..6143
    int b = g / (D_MODEL * RANK);
    int rem = g % (D_MODEL * RANK);                   // d*4 + r
    float arr = tanhf(a_p[rem * 2 + 0]) * 0.97f;
    float aii = tanhf(a_p[rem * 2 + 1]) * 0.97f;
#pragma unroll
    for (int s = 0; s < 5; s++) {                     // a^32
        float nr = arr * arr - aii * aii;
        float ni = 2.f * arr * aii;
        arr = nr; aii = ni;
    }
    float rr = 0.f, ri = 0.f;
    for (int c = 0; c < NC; c++) {
        size_t idx = (size_t)(c * BATCH + b) * (D_MODEL * RANK) + rem;
        float2 S = g_ps[idx];
        g_ps[idx] = make_float2(rr, ri);              // exclusive carry-in
        float nrr = arr * rr - aii * ri + S.x;
        float nri = arr * ri + aii * rr + S.y;
        rr = nrr; ri = nri;
    }
}

__global__ __launch_bounds__(256) void scan_pass2(const float* __restrict__ a_p,
                                                  const float* __restrict__ b_p,
                                                  const float* __restrict__ c_p) {
    const int c   = blockIdx.x;
    const int sl  = blockIdx.y;
    const int b   = blockIdx.z;
    const int d   = sl * 256 + threadIdx.x;

    float ar[RANK], ai[RANK], br_[RANK], bi[RANK], cr[RANK], ci[RANK];
#pragma unroll
    for (int r = 0; r < RANK; r++) {
        int idx = (d * RANK + r) * 2;
        ar[r]  = tanhf(a_p[idx + 0]) * 0.97f;
        ai[r]  = tanhf(a_p[idx + 1]) * 0.97f;
        br_[r] = tanhf(b_p[idx + 0]);
        bi[r]  = tanhf(b_p[idx + 1]);
        cr[r]  = tanhf(c_p[idx + 0]);
        ci[r]  = tanhf(c_p[idx + 1]);
    }

    float sr[RANK], si[RANK];
    const float2* ps = g_ps + ((size_t)(c * BATCH + b) * D_MODEL + d) * RANK;
#pragma unroll
    for (int r = 0; r < RANK; r++) { float2 v = ps[r]; sr[r] = v.x; si[r] = v.y; }

    const __half* up = g_u + ((size_t)(b * T_LEN + c * TL)) * N_IN + (size_t)d * 8;
    __half* yp = g_y + (size_t)(b * T_LEN + c * TL) * D_MODEL + d;

#pragma unroll 4
    for (int i = 0; i < TL; i++) {
        uint4 raw = *(const uint4*)(up);
        const __half2* hp = (const __half2*)&raw;
        float y = 0.f;
#pragma unroll
        for (int r = 0; r < RANK; r++) {
            float2 p = __half22float2(hp[r]);
            float nsr = ar[r] * sr[r] - ai[r] * si[r] + br_[r] * p.x - bi[r] * p.y;
            float nsi = ar[r] * si[r] + ai[r] * sr[r] + br_[r] * p.y + bi[r] * p.x;
            sr[r] = nsr; si[r] = nsi;
            y += cr[r] * nsr - ci[r] * nsi;
        }
        *yp = __float2half_rn(y);
        up += N_IN;
        yp += D_MODEL;
    }
}

// ---------------------------------------------------------------------------
extern "C" void kernel_launch(void* const* d_in, const int* in_sizes, int n_in,
                              void* d_out, int out_size) {
    const float* x      = (const float*)d_in[0];
    const float* norm_w = (const float*)d_in[1];
    const float* W_in   = (const float*)d_in[2];
    const float* W_out  = (const float*)d_in[3];
    const float* a_p    = (const float*)d_in[4];
    const float* b_p    = (const float*)d_in[5];
    const float* c_p    = (const float*)d_in[6];
    float* out = (float*)d_out;

    __half *u_ptr, *xn_ptr, *wih, *y_ptr, *woh;
    cudaGetSymbolAddress((void**)&u_ptr,  g_u);
    cudaGetSymbolAddress((void**)&xn_ptr, g_xn);
    cudaGetSymbolAddress((void**)&wih,    g_wi_h);
    cudaGetSymbolAddress((void**)&y_ptr,  g_y);
    cudaGetSymbolAddress((void**)&woh,    g_wo_h);

    static bool attr_set = false;
    if (!attr_set) {
        cudaFuncSetAttribute(gemm_f16<__half>, cudaFuncAttributeMaxDynamicSharedMemorySize,
                             NSTAGES * F16_STAGE);
        cudaFuncSetAttribute(gemm_f16<float>, cudaFuncAttributeMaxDynamicSharedMemorySize,
                             NSTAGES * F16_STAGE);
        attr_set = true;
    }

    // weight prep
    round_kernel_f16<<<(N_IN * D_MODEL) / 1024, 256>>>(W_in, wih);
    round_kernel_f16<<<(D_MODEL * D_MODEL) / 1024, 256>>>(W_out, woh);

    // RMSNorm -> fp16
    rmsnorm_kernel<<<NTOK, 256>>>(x, norm_w);

    // u = xn @ W_in^T  (M=4096, N=6144, K=768) -> fp16
    {
        dim3 grid(N_IN / GBN, NTOK / GBM);
        gemm_f16<__half><<<grid, 256, NSTAGES * F16_STAGE>>>(xn_ptr, wih, u_ptr,
                                                             N_IN, D_MODEL);
    }

    // scan: coalesced 3-kernel chunked scan -> y (fp16)
    {
        dim3 grid(NC, 3, BATCH);
        scan_pass1<<<grid, 256>>>(a_p, b_p);
        scan_carry<<<(BATCH * D_MODEL * RANK) / 256, 256>>>(a_p);
        scan_pass2<<<grid, 256>>>(a_p, b_p, c_p);
    }

    // out = y @ W_out^T (M=4096, N=768, K=768) -> fp32
    {
        dim3 grid(D_MODEL / GBN, NTOK / GBM);
        gemm_f16<float><<<grid, 256, NSTAGES * F16_STAGE>>>(y_ptr, woh, out,
                                                            D_MODEL, D_MODEL);
    }
}

// round 16
// speedup vs baseline: 6.6410x; 1.0420x over previous
#include <cuda_runtime.h>
#include <cuda_bf16.h>
#include <cuda_fp16.h>
#include <cstdint>

#define D_MODEL 768
#define RANK    4
#define BATCH   2
#define T_LEN   2048
#define NTOK    (BATCH * T_LEN)        // 4096
#define N_IN    (D_MODEL * RANK * 2)   // 6144
#define NC      64                     // scan chunks over time
#define TL      (T_LEN / NC)           // 32 timesteps per chunk

// ---------------- scratch (device globals; allocation-free rule) ----------------
__device__ __half  g_u   [(size_t)NTOK * N_IN];      // 50.3 MB fp16
__device__ __half  g_xn  [(size_t)NTOK * D_MODEL];
__device__ __half  g_y   [(size_t)NTOK * D_MODEL];
__device__ __half  g_wi_h[(size_t)N_IN * D_MODEL];   // W_in fp16
__device__ __half  g_wo_h[(size_t)D_MODEL * D_MODEL];// W_out fp16
// per-chunk partial states / carry-ins: [c][b][d][r] float2 (3.1 MB)
__device__ float2  g_ps  [(size_t)NC * BATCH * D_MODEL * RANK];

// ---------------------------------------------------------------------------
// helpers
// ---------------------------------------------------------------------------
__device__ __forceinline__ void ldsm_x4(uint32_t addr, uint32_t& r0, uint32_t& r1,
                                        uint32_t& r2, uint32_t& r3) {
    asm volatile("ldmatrix.sync.aligned.m8n8.x4.shared.b16 {%0,%1,%2,%3}, [%4];"
                 : "=r"(r0), "=r"(r1), "=r"(r2), "=r"(r3) : "r"(addr));
}

__device__ __forceinline__ void mma_f16(float* c, const uint32_t* a, const uint32_t* b) {
    asm volatile(
        "mma.sync.aligned.m16n8k16.row.col.f32.f16.f16.f32 "
        "{%0,%1,%2,%3}, {%4,%5,%6,%7}, {%8,%9}, {%0,%1,%2,%3};"
        : "+f"(c[0]), "+f"(c[1]), "+f"(c[2]), "+f"(c[3])
        : "r"(a[0]), "r"(a[1]), "r"(a[2]), "r"(a[3]), "r"(b[0]), "r"(b[1]));
}

#define CP_ASYNC16(dst, src) \
    asm volatile("cp.async.cg.shared.global [%0], [%1], 16;" :: "r"(dst), "l"(src))

// ---------------------------------------------------------------------------
// weight rounding: fp32 -> fp16
// ---------------------------------------------------------------------------
__global__ __launch_bounds__(256) void round_kernel_f16(const float* __restrict__ src,
                                                        __half* __restrict__ dst) {
    int i = (blockIdx.x * 256 + threadIdx.x) * 4;
    float4 v = *(const float4*)(src + i);
    *(__half2*)(dst + i)     = __half2(__float2half_rn(v.x), __float2half_rn(v.y));
    *(__half2*)(dst + i + 2) = __half2(__float2half_rn(v.z), __float2half_rn(v.w));
}

// ---------------------------------------------------------------------------
// RMSNorm -> fp16
// ---------------------------------------------------------------------------
__global__ __launch_bounds__(256) void rmsnorm_kernel(const float* __restrict__ x,
                                                      const float* __restrict__ w) {
    int tok = blockIdx.x;
    const float* xr = x + (size_t)tok * D_MODEL;
    int t = threadIdx.x;

    float v[3];
    float ss = 0.f;
#pragma unroll
    for (int i = 0; i < 3; i++) { v[i] = xr[t + 256 * i]; ss += v[i] * v[i]; }

    __shared__ float red[8];
#pragma unroll
    for (int off = 16; off; off >>= 1) ss += __shfl_down_sync(0xffffffffu, ss, off);
    if ((t & 31) == 0) red[t >> 5] = ss;
    __syncthreads();
    if (t < 8) {
        float s = red[t];
#pragma unroll
        for (int off = 4; off; off >>= 1) s += __shfl_down_sync(0xffu, s, off);
        if (t == 0) red[0] = s;
    }
    __syncthreads();
    float scale = rsqrtf(red[0] * (1.0f / D_MODEL) + 1e-6f);
#pragma unroll
    for (int i = 0; i < 3; i++) {
        int idx = tok * D_MODEL + t + 256 * i;
        g_xn[idx] = __float2half_rn(v[i] * scale * w[t + 256 * i]);
    }
}

// ---------------------------------------------------------------------------
// single-term fp16 GEMM (NT): C[m,n] = sum_k A[m,k] * B[n,k], fp32 accum
// BM=128, BN=128, BK=64, 3-stage cp.async, 256 threads, warps 2(M)x4(N).
// Smem tiles: 128B rows (64 fp16 = one BK), 8 chunks of 16B, xor(&7) swizzle.
// 12 mainloop iterations for K=768 (half the barriers of BK=32).
// ---------------------------------------------------------------------------
#define GBM 128
#define GBN 128
#define GBK 64
#define F16_A_BYTES (GBM * 128)
#define F16_B_BYTES (GBN * 128)
#define F16_STAGE   (F16_A_BYTES + F16_B_BYTES)      // 32768
#define NSTAGES 3

template <typename OutT>
__global__ __launch_bounds__(256, 2) void gemm_f16(
    const __half* __restrict__ A, const __half* __restrict__ B,
    OutT* __restrict__ C, int N, int K) {

    extern __shared__ char smem[];
    const uint32_t smem_u32 = (uint32_t)__cvta_generic_to_shared(smem);

    const int t    = threadIdx.x;
    const int lane = t & 31;
    const int wid  = t >> 5;
    const int wm   = wid & 1;
    const int wn   = wid >> 1;

    const int bm = blockIdx.y * GBM;
    const int bn = blockIdx.x * GBN;

    const int lc   = t & 7;           // 16B chunk within 128B row
    const int row0 = t >> 3;          // 0..31
    const int koff = lc * 8;

    float acc[4][4][4];
#pragma unroll
    for (int i = 0; i < 4; i++)
#pragma unroll
        for (int j = 0; j < 4; j++)
#pragma unroll
            for (int q = 0; q < 4; q++) acc[i][j][q] = 0.f;

    const int KI = K / GBK;           // 12

    auto load_stage = [&](int stage, int k0) {
        uint32_t sA = smem_u32 + stage * F16_STAGE;
        uint32_t sB = sA + F16_A_BYTES;
#pragma unroll
        for (int p = 0; p < 4; p++) {
            int m = row0 + p * 32;
            const __half* srcA = A + (size_t)(bm + m) * K + k0 + koff;
            CP_ASYNC16(sA + m * 128 + ((lc ^ (m & 7)) * 16), srcA);
        }
#pragma unroll
        for (int p = 0; p < 4; p++) {
            int n = row0 + p * 32;
            const __half* srcB = B + (size_t)(bn + n) * K + k0 + koff;
            CP_ASYNC16(sB + n * 128 + ((lc ^ (n & 7)) * 16), srcB);
        }
    };

    load_stage(0, 0);
    asm volatile("cp.async.commit_group;" ::: "memory");
    load_stage(1, GBK);
    asm volatile("cp.async.commit_group;" ::: "memory");

    for (int it = 0; it < KI; ++it) {
        asm volatile("cp.async.wait_group 1;" ::: "memory");
        __syncthreads();

        int ldk = it + 2;
        if (ldk < KI) load_stage(ldk % NSTAGES, ldk * GBK);
        asm volatile("cp.async.commit_group;" ::: "memory");

        uint32_t sA = smem_u32 + (it % NSTAGES) * F16_STAGE;
        uint32_t sB = sA + F16_A_BYTES;

#pragma unroll
        for (int kst = 0; kst < 4; kst++) {
            uint32_t af[4][4];
#pragma unroll
            for (int i = 0; i < 4; i++) {
                int row = wm * 64 + i * 16 + (lane & 15);
                int ch  = kst * 2 + (lane >> 4);
                ldsm_x4(sA + row * 128 + ((ch ^ (row & 7)) * 16),
                        af[i][0], af[i][1], af[i][2], af[i][3]);
            }
            uint32_t bf[4][2];
#pragma unroll
            for (int j = 0; j < 2; j++) {
                int row = wn * 32 + j * 16 + (lane & 7) + ((lane >> 4) << 3);
                int ch  = kst * 2 + ((lane >> 3) & 1);
                uint32_t r0, r1, r2, r3;
                ldsm_x4(sB + row * 128 + ((ch ^ (row & 7)) * 16), r0, r1, r2, r3);
                bf[2 * j][0] = r0; bf[2 * j][1] = r1;
                bf[2 * j + 1][0] = r2; bf[2 * j + 1][1] = r3;
            }
#pragma unroll
            for (int i = 0; i < 4; i++)
#pragma unroll
                for (int j = 0; j < 4; j++)
                    mma_f16(acc[i][j], af[i], bf[j]);
        }
    }

#pragma unroll
    for (int i = 0; i < 4; i++) {
        int m0 = bm + wm * 64 + i * 16 + (lane >> 2);
#pragma unroll
        for (int j = 0; j < 4; j++) {
            int n0 = bn + wn * 32 + j * 8 + (lane & 3) * 2;
            if constexpr (sizeof(OutT) == 2) {
                *(__half2*)((__half*)C + (size_t)m0 * N + n0) =
                    __floats2half2_rn(acc[i][j][0], acc[i][j][1]);
                *(__half2*)((__half*)C + (size_t)(m0 + 8) * N + n0) =
                    __floats2half2_rn(acc[i][j][2], acc[i][j][3]);
            } else {
                *(float2*)((float*)C + (size_t)m0 * N + n0) =
                    make_float2(acc[i][j][0], acc[i][j][1]);
                *(float2*)((float*)C + (size_t)(m0 + 8) * N + n0) =
                    make_float2(acc[i][j][2], acc[i][j][3]);
            }
        }
    }
}

// ---------------------------------------------------------------------------
// SCAN, coalesced layout. Thread = one d-channel (4 complex ranks, 16B/t).
// ---------------------------------------------------------------------------
__global__ __launch_bounds__(256) void scan_pass1(const float* __restrict__ a_p,
                                                  const float* __restrict__ b_p) {
    const int c   = blockIdx.x;
    const int sl  = blockIdx.y;
    const int b   = blockIdx.z;
    const int d   = sl * 256 + threadIdx.x;

    float ar[RANK], ai[RANK], br_[RANK], bi[RANK];
#pragma unroll
    for (int r = 0; r < RANK; r++) {
        int idx = (d * RANK + r) * 2;
        ar[r]  = tanhf(a_p[idx + 0]) * 0.97f;
        ai[r]  = tanhf(a_p[idx + 1]) * 0.97f;
        br_[r] = tanhf(b_p[idx + 0]);
        bi[r]  = tanhf(b_p[idx + 1]);
    }

    const __half* up = g_u + ((size_t)(b * T_LEN + c * TL)) * N_IN + (size_t)d * 8;

    float sr[RANK] = {0, 0, 0, 0}, si[RANK] = {0, 0, 0, 0};
#pragma unroll 4
    for (int i = 0; i < TL; i++) {
        uint4 raw = *(const uint4*)(up);
        const __half2* hp = (const __half2*)&raw;
#pragma unroll
        for (int r = 0; r < RANK; r++) {
            float2 p = __half22float2(hp[r]);
            float nsr = ar[r] * sr[r] - ai[r] * si[r] + br_[r] * p.x - bi[r] * p.y;
            float nsi = ar[r] * si[r] + ai[r] * sr[r] + br_[r] * p.y + bi[r] * p.x;
            sr[r] = nsr; si[r] = nsi;
        }
        up += N_IN;
    }

    float2* ps = g_ps + ((size_t)(c * BATCH + b) * D_MODEL + d) * RANK;
#pragma unroll
    for (int r = 0; r < RANK; r++) ps[r] = make_float2(sr[r], si[r]);
}

__global__ __launch_bounds__(256) void scan_carry(const float* __restrict__ a_p) {
    int g = blockIdx.x * 256 + threadIdx.x;           // 0..6143
    int b = g / (D_MODEL * RANK);
    int rem = g % (D_MODEL * RANK);                   // d*4 + r
    float arr = tanhf(a_p[rem * 2 + 0]) * 0.97f;
    float aii = tanhf(a_p[rem * 2 + 1]) * 0.97f;
#pragma unroll
    for (int s = 0; s < 5; s++) {                     // a^32
        float nr = arr * arr - aii * aii;
        float ni = 2.f * arr * aii;
        arr = nr; aii = ni;
    }
    float rr = 0.f, ri = 0.f;
    for (int c = 0; c < NC; c++) {
        size_t idx = (size_t)(c * BATCH + b) * (D_MODEL * RANK) + rem;
        float2 S = g_ps[idx];
        g_ps[idx] = make_float2(rr, ri);              // exclusive carry-in
        float nrr = arr * rr - aii * ri + S.x;
        float nri = arr * ri + aii * rr + S.y;
        rr = nrr; ri = nri;
    }
}

__global__ __launch_bounds__(256) void scan_pass2(const float* __restrict__ a_p,
                                                  const float* __restrict__ b_p,
                                                  const float* __restrict__ c_p) {
    const int c   = blockIdx.x;
    const int sl  = blockIdx.y;
    const int b   = blockIdx.z;
    const int d   = sl * 256 + threadIdx.x;

    float ar[RANK], ai[RANK], br_[RANK], bi[RANK], cr[RANK], ci[RANK];
#pragma unroll
    for (int r = 0; r < RANK; r++) {
        int idx = (d * RANK + r) * 2;
        ar[r]  = tanhf(a_p[idx + 0]) * 0.97f;
        ai[r]  = tanhf(a_p[idx + 1]) * 0.97f;
        br_[r] = tanhf(b_p[idx + 0]);
        bi[r]  = tanhf(b_p[idx + 1]);
        cr[r]  = tanhf(c_p[idx + 0]);
        ci[r]  = tanhf(c_p[idx + 1]);
    }

    float sr[RANK], si[RANK];
    const float2* ps = g_ps + ((size_t)(c * BATCH + b) * D_MODEL + d) * RANK;
#pragma unroll
    for (int r = 0; r < RANK; r++) { float2 v = ps[r]; sr[r] = v.x; si[r] = v.y; }

    const __half* up = g_u + ((size_t)(b * T_LEN + c * TL)) * N_IN + (size_t)d * 8;
    __half* yp = g_y + (size_t)(b * T_LEN + c * TL) * D_MODEL + d;

#pragma unroll 4
    for (int i = 0; i < TL; i++) {
        uint4 raw = *(const uint4*)(up);
        const __half2* hp = (const __half2*)&raw;
        float y = 0.f;
#pragma unroll
        for (int r = 0; r < RANK; r++) {
            float2 p = __half22float2(hp[r]);
            float nsr = ar[r] * sr[r] - ai[r] * si[r] + br_[r] * p.x - bi[r] * p.y;
            float nsi = ar[r] * si[r] + ai[r] * sr[r] + br_[r] * p.y + bi[r] * p.x;
            sr[r] = nsr; si[r] = nsi;
            y += cr[r] * nsr - ci[r] * nsi;
        }
        *yp = __float2half_rn(y);
        up += N_IN;
        yp += D_MODEL;
    }
}

// ---------------------------------------------------------------------------
extern "C" void kernel_launch(void* const* d_in, const int* in_sizes, int n_in,
                              void* d_out, int out_size) {
    const float* x      = (const float*)d_in[0];
    const float* norm_w = (const float*)d_in[1];
    const float* W_in   = (const float*)d_in[2];
    const float* W_out  = (const float*)d_in[3];
    const float* a_p    = (const float*)d_in[4];
    const float* b_p    = (const float*)d_in[5];
    const float* c_p    = (const float*)d_in[6];
    float* out = (float*)d_out;

    __half *u_ptr, *xn_ptr, *wih, *y_ptr, *woh;
    cudaGetSymbolAddress((void**)&u_ptr,  g_u);
    cudaGetSymbolAddress((void**)&xn_ptr, g_xn);
    cudaGetSymbolAddress((void**)&wih,    g_wi_h);
    cudaGetSymbolAddress((void**)&y_ptr,  g_y);
    cudaGetSymbolAddress((void**)&woh,    g_wo_h);

    static bool attr_set = false;
    if (!attr_set) {
        cudaFuncSetAttribute(gemm_f16<__half>, cudaFuncAttributeMaxDynamicSharedMemorySize,
                             NSTAGES * F16_STAGE);
        cudaFuncSetAttribute(gemm_f16<float>, cudaFuncAttributeMaxDynamicSharedMemorySize,
                             NSTAGES * F16_STAGE);
        attr_set = true;
    }

    // weight prep
    round_kernel_f16<<<(N_IN * D_MODEL) / 1024, 256>>>(W_in, wih);
    round_kernel_f16<<<(D_MODEL * D_MODEL) / 1024, 256>>>(W_out, woh);

    // RMSNorm -> fp16
    rmsnorm_kernel<<<NTOK, 256>>>(x, norm_w);

    // u = xn @ W_in^T  (M=4096, N=6144, K=768) -> fp16
    {
        dim3 grid(N_IN / GBN, NTOK / GBM);
        gemm_f16<__half><<<grid, 256, NSTAGES * F16_STAGE>>>(xn_ptr, wih, u_ptr,
                                                             N_IN, D_MODEL);
    }

    // scan: coalesced 3-kernel chunked scan -> y (fp16)
    {
        dim3 grid(NC, 3, BATCH);
        scan_pass1<<<grid, 256>>>(a_p, b_p);
        scan_carry<<<(BATCH * D_MODEL * RANK) / 256, 256>>>(a_p);
        scan_pass2<<<grid, 256>>>(a_p, b_p, c_p);
    }

    // out = y @ W_out^T (M=4096, N=768, K=768) -> fp32
    {
        dim3 grid(D_MODEL / GBN, NTOK / GBM);
        gemm_f16<float><<<grid, 256, NSTAGES * F16_STAGE>>>(y_ptr, woh, out,
                                                            D_MODEL, D_MODEL);
    }
}